// round 1
// baseline (speedup 1.0000x reference)
#include <cuda_runtime.h>
#include <math.h>
#include <stdint.h>

// Problem dims
#define B_    512
#define SQ_   49
#define SK_   50
#define DIMG_ 2048
#define DTXT_ 768
#define D_    512
#define H_    4
#define DH_   128
#define MI_   (B_*SQ_)   // 25088 image-token rows
#define MT_   (B_*SK_)   // 25600 text-token rows

// Scratch (static __device__ — no allocations allowed)
__device__ float g_Pimg[MI_*D_];
__device__ float g_Ptxt[MT_*D_];
__device__ float g_q[MI_*D_];
__device__ float g_k[MT_*D_];
__device__ float g_v[MT_*D_];
__device__ float g_a[B_*H_*SQ_*SK_];
__device__ float g_o[MI_*D_];
__device__ float g_n1[B_*D_];
__device__ float g_n2[B_*D_];

__device__ __forceinline__ float gelu_f(float x) {
    return 0.5f * x * (1.0f + erff(x * 0.7071067811865476f));
}

// ---------------------------------------------------------------------------
// Tiled SGEMM: C[M,N] = op(A)[M,K] @ W[K,N] + bias (+ Res)
// ALOAD: 0 = plain row-major A, 1 = gelu(A) on load, 2 = image_features
//        transposed-on-the-fly: A[m,k] = IF[b*DIMG*SQ + k*SQ + q], m=b*SQ+q
// Tile 128x128x8, 256 threads, 8x8 per-thread microtile, double-buffered smem.
// Requires M%128==0, N%128==0, K%8==0 (all shapes here satisfy this).
// ---------------------------------------------------------------------------
template<int ALOAD, bool RES>
__global__ __launch_bounds__(256, 2) void sgemm_kernel(
    const float* __restrict__ A, const float* __restrict__ W,
    const float* __restrict__ bias, const float* __restrict__ Res,
    float* __restrict__ C, int M, int N, int K)
{
    __shared__ float As[2][8][128];
    __shared__ float Bs[2][8][128];
    const int tid = threadIdx.x;
    const int m0 = blockIdx.y * 128;
    const int n0 = blockIdx.x * 128;

    int a_m, a_k;
    long a_base;
    if (ALOAD == 2) {
        a_m = tid & 127;
        a_k = (tid >> 7) << 2;
        int m  = m0 + a_m;
        int bb = m / SQ_;
        int qq = m - bb * SQ_;
        a_base = (long)bb * (DIMG_ * SQ_) + qq;
    } else {
        a_m = tid >> 1;
        a_k = (tid & 1) << 2;
        a_base = (long)(m0 + a_m) * K + a_k;
    }
    const int  b_k    = tid >> 5;
    const int  b_n    = (tid & 31) << 2;
    const long b_base = (long)b_k * N + n0 + b_n;

    // Fragment mapping: warp grid 4x2 (32x64 warp tiles), lane grid 4x8.
    const int wn = tid >> 7;
    const int wm = (tid >> 5) & 3;
    const int lm = (tid >> 3) & 3;
    const int ln = tid & 7;
    const int mf = wm * 32 + lm * 8;
    const int nf = wn * 64 + ln * 8;

    float acc[8][8];
    #pragma unroll
    for (int i = 0; i < 8; i++)
        #pragma unroll
        for (int j = 0; j < 8; j++) acc[i][j] = 0.f;

    const int nt = K >> 3;

    // Prologue: tile 0
    if (ALOAD == 2) {
        #pragma unroll
        for (int i = 0; i < 4; i++)
            As[0][a_k + i][a_m] = A[a_base + (long)(a_k + i) * SQ_];
    } else {
        float4 va = *reinterpret_cast<const float4*>(A + a_base);
        if (ALOAD == 1) { va.x = gelu_f(va.x); va.y = gelu_f(va.y); va.z = gelu_f(va.z); va.w = gelu_f(va.w); }
        As[0][a_k+0][a_m] = va.x; As[0][a_k+1][a_m] = va.y;
        As[0][a_k+2][a_m] = va.z; As[0][a_k+3][a_m] = va.w;
    }
    {
        float4 vb = *reinterpret_cast<const float4*>(W + b_base);
        *reinterpret_cast<float4*>(&Bs[0][b_k][b_n]) = vb;
    }
    __syncthreads();

    for (int t = 0; t < nt; t++) {
        const int cur = t & 1, nxt = cur ^ 1;
        if (t + 1 < nt) {
            const int kt = (t + 1) << 3;
            if (ALOAD == 2) {
                #pragma unroll
                for (int i = 0; i < 4; i++)
                    As[nxt][a_k + i][a_m] = A[a_base + (long)(kt + a_k + i) * SQ_];
            } else {
                float4 va = *reinterpret_cast<const float4*>(A + a_base + kt);
                if (ALOAD == 1) { va.x = gelu_f(va.x); va.y = gelu_f(va.y); va.z = gelu_f(va.z); va.w = gelu_f(va.w); }
                As[nxt][a_k+0][a_m] = va.x; As[nxt][a_k+1][a_m] = va.y;
                As[nxt][a_k+2][a_m] = va.z; As[nxt][a_k+3][a_m] = va.w;
            }
            float4 vb = *reinterpret_cast<const float4*>(W + b_base + (long)kt * N);
            *reinterpret_cast<float4*>(&Bs[nxt][b_k][b_n]) = vb;
        }
        #pragma unroll
        for (int kk = 0; kk < 8; kk++) {
            float4 a0 = *reinterpret_cast<const float4*>(&As[cur][kk][mf]);
            float4 a1 = *reinterpret_cast<const float4*>(&As[cur][kk][mf + 4]);
            float4 b0 = *reinterpret_cast<const float4*>(&Bs[cur][kk][nf]);
            float4 b1 = *reinterpret_cast<const float4*>(&Bs[cur][kk][nf + 4]);
            float ar[8] = {a0.x, a0.y, a0.z, a0.w, a1.x, a1.y, a1.z, a1.w};
            float br[8] = {b0.x, b0.y, b0.z, b0.w, b1.x, b1.y, b1.z, b1.w};
            #pragma unroll
            for (int i = 0; i < 8; i++)
                #pragma unroll
                for (int j = 0; j < 8; j++)
                    acc[i][j] = fmaf(ar[i], br[j], acc[i][j]);
        }
        __syncthreads();
    }

    #pragma unroll
    for (int i = 0; i < 8; i++) {
        const long row = m0 + mf + i;
        #pragma unroll
        for (int jj = 0; jj < 2; jj++) {
            const int col = n0 + nf + jj * 4;
            float4 bv = *reinterpret_cast<const float4*>(bias + col);
            float4 r;
            r.x = acc[i][jj*4+0] + bv.x;
            r.y = acc[i][jj*4+1] + bv.y;
            r.z = acc[i][jj*4+2] + bv.z;
            r.w = acc[i][jj*4+3] + bv.w;
            if (RES) {
                float4 rv = *reinterpret_cast<const float4*>(Res + row * N + col);
                r.x += rv.x; r.y += rv.y; r.z += rv.z; r.w += rv.w;
            }
            *reinterpret_cast<float4*>(C + row * N + col) = r;
        }
    }
}

// ---------------------------------------------------------------------------
// In-place LayerNorm over last dim (512). One block per row, 128 threads.
// ---------------------------------------------------------------------------
__global__ __launch_bounds__(128) void ln_kernel(
    float* __restrict__ X, const float* __restrict__ g, const float* __restrict__ be)
{
    const long row = blockIdx.x;
    float* xr = X + row * D_;
    const int t = threadIdx.x;
    float4 v = *reinterpret_cast<const float4*>(xr + t * 4);
    float s  = v.x + v.y + v.z + v.w;
    float sq = v.x*v.x + v.y*v.y + v.z*v.z + v.w*v.w;
    #pragma unroll
    for (int o = 16; o; o >>= 1) {
        s  += __shfl_xor_sync(0xffffffffu, s,  o);
        sq += __shfl_xor_sync(0xffffffffu, sq, o);
    }
    __shared__ float sh[8];
    if ((t & 31) == 0) { sh[t >> 5] = s; sh[4 + (t >> 5)] = sq; }
    __syncthreads();
    const float ts = sh[0] + sh[1] + sh[2] + sh[3];
    const float tq = sh[4] + sh[5] + sh[6] + sh[7];
    const float mu  = ts * (1.f / 512.f);
    const float var = tq * (1.f / 512.f) - mu * mu;
    const float inv = rsqrtf(var + 1e-5f);
    float4 gv = *reinterpret_cast<const float4*>(g  + t * 4);
    float4 bv = *reinterpret_cast<const float4*>(be + t * 4);
    v.x = gv.x * (v.x - mu) * inv + bv.x;
    v.y = gv.y * (v.y - mu) * inv + bv.y;
    v.z = gv.z * (v.z - mu) * inv + bv.z;
    v.w = gv.w * (v.w - mu) * inv + bv.w;
    *reinterpret_cast<float4*>(xr + t * 4) = v;
}

// ---------------------------------------------------------------------------
// Attention: one block per (b,h). scores -> softmax -> o. Writes a (probs) + o.
// ---------------------------------------------------------------------------
__global__ __launch_bounds__(256) void attn_kernel(
    const float* __restrict__ q, const float* __restrict__ k,
    const float* __restrict__ v, float* __restrict__ a, float* __restrict__ o)
{
    const int bh = blockIdx.x;
    const int b  = bh >> 2;
    const int h  = bh & 3;
    __shared__ float kv[SK_ * DH_];   // 6400 floats
    __shared__ float s[SQ_ * SK_];    // 2450 floats
    const int tid = threadIdx.x;

    const float* kb = k + (long)b * SK_ * D_ + h * DH_;
    for (int i = tid; i < SK_ * DH_; i += 256) {
        int r = i >> 7, d = i & 127;
        kv[i] = kb[(long)r * D_ + d];
    }
    __syncthreads();

    const float* qb = q + (long)b * SQ_ * D_ + h * DH_;
    for (int i = tid; i < SQ_ * SK_; i += 256) {
        int qi = i / SK_, ki = i - qi * SK_;
        const float* qr = qb + (long)qi * D_;
        const float* kr = kv + ki * DH_;
        float accv = 0.f;
        #pragma unroll 8
        for (int d = 0; d < DH_; d++) accv += qr[d] * kr[d];
        s[i] = accv * 0.08838834764831845f;  // 1/sqrt(128)
    }
    __syncthreads();

    // Load V over K's smem; softmax rows in parallel (independent data).
    const float* vb = v + (long)b * SK_ * D_ + h * DH_;
    for (int i = tid; i < SK_ * DH_; i += 256) {
        int r = i >> 7, d = i & 127;
        kv[i] = vb[(long)r * D_ + d];
    }
    const int w = tid >> 5, lane = tid & 31;
    for (int row = w; row < SQ_; row += 8) {
        float mx = -1e30f;
        for (int c = lane; c < SK_; c += 32) mx = fmaxf(mx, s[row * SK_ + c]);
        #pragma unroll
        for (int off = 16; off; off >>= 1) mx = fmaxf(mx, __shfl_xor_sync(0xffffffffu, mx, off));
        float sum = 0.f;
        for (int c = lane; c < SK_; c += 32) {
            float e = __expf(s[row * SK_ + c] - mx);
            s[row * SK_ + c] = e;
            sum += e;
        }
        #pragma unroll
        for (int off = 16; off; off >>= 1) sum += __shfl_xor_sync(0xffffffffu, sum, off);
        const float inv = 1.f / sum;
        float* arow = a + ((long)(b * H_ + h) * SQ_ + row) * SK_;
        for (int c = lane; c < SK_; c += 32) {
            float p = s[row * SK_ + c] * inv;
            s[row * SK_ + c] = p;
            arow[c] = p;
        }
    }
    __syncthreads();

    float* ob = o + (long)b * SQ_ * D_ + h * DH_;
    for (int i = tid; i < SQ_ * DH_; i += 256) {
        int qi = i >> 7, d = i & 127;
        const float* sr = s + qi * SK_;
        float accv = 0.f;
        #pragma unroll
        for (int kk = 0; kk < SK_; kk++) accv += sr[kk] * kv[kk * DH_ + d];
        ob[(long)qi * D_ + d] = accv;
    }
}

// attn_weights[b,q,k] = mean_h a[b,h,q,k]
__global__ void meanh_kernel(const float* __restrict__ a, float* __restrict__ out)
{
    const int idx = blockIdx.x * 256 + threadIdx.x;
    if (idx >= B_ * SQ_ * SK_) return;
    const int b = idx / (SQ_ * SK_);
    const int r = idx - b * (SQ_ * SK_);
    float sum = 0.f;
    #pragma unroll
    for (int h = 0; h < H_; h++)
        sum += a[((long)(b * H_ + h)) * (SQ_ * SK_) + r];
    out[idx] = sum * 0.25f;
}

// n1 = normalize(mean_q attn_out[b]); n2 = normalize(pt[b,0,:])
__global__ __launch_bounds__(256) void norm_kernel(
    const float* __restrict__ ao, const float* __restrict__ pt,
    float* __restrict__ n1, float* __restrict__ n2)
{
    const int b = blockIdx.x;
    const int t = threadIdx.x;
    float v1[2], v2[2];
    float sq1 = 0.f, sq2 = 0.f;
    #pragma unroll
    for (int j = 0; j < 2; j++) {
        const int d = t + j * 256;
        const float* base = ao + (long)b * SQ_ * D_ + d;
        float sum = 0.f;
        #pragma unroll
        for (int qq = 0; qq < SQ_; qq++) sum += base[(long)qq * D_];
        sum *= (1.f / 49.f);
        v1[j] = sum; sq1 += sum * sum;
        const float c = pt[(long)b * SK_ * D_ + d];
        v2[j] = c; sq2 += c * c;
    }
    #pragma unroll
    for (int o = 16; o; o >>= 1) {
        sq1 += __shfl_xor_sync(0xffffffffu, sq1, o);
        sq2 += __shfl_xor_sync(0xffffffffu, sq2, o);
    }
    __shared__ float s1[8], s2[8];
    if ((t & 31) == 0) { s1[t >> 5] = sq1; s2[t >> 5] = sq2; }
    __syncthreads();
    float t1 = 0.f, t2 = 0.f;
    #pragma unroll
    for (int i = 0; i < 8; i++) { t1 += s1[i]; t2 += s2[i]; }
    const float i1 = rsqrtf(t1), i2 = rsqrtf(t2);
    #pragma unroll
    for (int j = 0; j < 2; j++) {
        const int d = t + j * 256;
        n1[(long)b * D_ + d] = v1[j] * i1;
        n2[(long)b * D_ + d] = v2[j] * i2;
    }
}

// score[i,j] = dot(n1[i,:], n2[j,:]); 512x512x512
__global__ __launch_bounds__(256) void score_kernel(
    const float* __restrict__ n1, const float* __restrict__ n2, float* __restrict__ out)
{
    __shared__ float As[16][17];
    __shared__ float Bs[16][17];
    const int tx = threadIdx.x & 15;
    const int ty = threadIdx.x >> 4;
    const int i0 = blockIdx.y * 16;
    const int j0 = blockIdx.x * 16;
    float acc = 0.f;
    for (int k0 = 0; k0 < D_; k0 += 16) {
        As[ty][tx] = n1[(long)(i0 + ty) * D_ + k0 + tx];
        Bs[ty][tx] = n2[(long)(j0 + ty) * D_ + k0 + tx];
        __syncthreads();
        #pragma unroll
        for (int e = 0; e < 16; e++) acc += As[ty][e] * Bs[tx][e];
        __syncthreads();
    }
    out[(long)(i0 + ty) * B_ + j0 + tx] = acc;
}

// ---------------------------------------------------------------------------
extern "C" void kernel_launch(void* const* d_in, const int* in_sizes, int n_in,
                              void* d_out, int out_size)
{
    (void)in_sizes; (void)n_in; (void)out_size;
    const float* IF  = (const float*)d_in[0];
    const float* TXT = (const float*)d_in[1];
    const float* Wi1 = (const float*)d_in[2];
    const float* bi1 = (const float*)d_in[3];
    const float* Wi2 = (const float*)d_in[4];
    const float* bi2 = (const float*)d_in[5];
    const float* gi  = (const float*)d_in[6];
    const float* bei = (const float*)d_in[7];
    const float* Wt1 = (const float*)d_in[8];
    const float* bt1 = (const float*)d_in[9];
    const float* Wt2 = (const float*)d_in[10];
    const float* bt2 = (const float*)d_in[11];
    const float* gt  = (const float*)d_in[12];
    const float* bet = (const float*)d_in[13];
    const float* Wq  = (const float*)d_in[14];
    const float* bq  = (const float*)d_in[15];
    const float* Wk  = (const float*)d_in[16];
    const float* bk  = (const float*)d_in[17];
    const float* Wv  = (const float*)d_in[18];
    const float* bv  = (const float*)d_in[19];
    const float* Wo  = (const float*)d_in[20];
    const float* bo  = (const float*)d_in[21];

    float* out       = (float*)d_out;
    float* score     = out;                                 // 512*512
    float* attn_out  = score + (long)B_ * B_;               // 25088*512
    float* attn_w    = attn_out + (long)MI_ * D_;           // 512*49*50
    float* pi        = attn_w + (long)B_ * SQ_ * SK_;       // 25088*512
    float* pt        = pi + (long)MI_ * D_;                 // 25600*512

    float *Pimg, *Ptxt, *qb_, *kb_, *vb_, *ab_, *ob_, *n1_, *n2_;
    cudaGetSymbolAddress((void**)&Pimg, g_Pimg);
    cudaGetSymbolAddress((void**)&Ptxt, g_Ptxt);
    cudaGetSymbolAddress((void**)&qb_,  g_q);
    cudaGetSymbolAddress((void**)&kb_,  g_k);
    cudaGetSymbolAddress((void**)&vb_,  g_v);
    cudaGetSymbolAddress((void**)&ab_,  g_a);
    cudaGetSymbolAddress((void**)&ob_,  g_o);
    cudaGetSymbolAddress((void**)&n1_,  g_n1);
    cudaGetSymbolAddress((void**)&n2_,  g_n2);

    const dim3 gI(D_ / 128, MI_ / 128);   // (4, 196)
    const dim3 gT(D_ / 128, MT_ / 128);   // (4, 200)

    // Image head: P = img @ Wi1 + bi1 ; H = gelu(P) @ Wi2 + bi2 + P ; LN -> pi
    sgemm_kernel<2, false><<<gI, 256>>>(IF,   Wi1, bi1, nullptr, Pimg, MI_, D_, DIMG_);
    sgemm_kernel<1, true ><<<gI, 256>>>(Pimg, Wi2, bi2, Pimg,    pi,   MI_, D_, D_);
    ln_kernel<<<MI_, 128>>>(pi, gi, bei);

    // Text head
    sgemm_kernel<0, false><<<gT, 256>>>(TXT,  Wt1, bt1, nullptr, Ptxt, MT_, D_, DTXT_);
    sgemm_kernel<1, true ><<<gT, 256>>>(Ptxt, Wt2, bt2, Ptxt,    pt,   MT_, D_, D_);
    ln_kernel<<<MT_, 128>>>(pt, gt, bet);

    // QKV
    sgemm_kernel<0, false><<<gI, 256>>>(pi, Wq, bq, nullptr, qb_, MI_, D_, D_);
    sgemm_kernel<0, false><<<gT, 256>>>(pt, Wk, bk, nullptr, kb_, MT_, D_, D_);
    sgemm_kernel<0, false><<<gT, 256>>>(pt, Wv, bv, nullptr, vb_, MT_, D_, D_);

    // Attention + head-mean of probs
    attn_kernel<<<B_ * H_, 256>>>(qb_, kb_, vb_, ab_, ob_);
    meanh_kernel<<<(B_ * SQ_ * SK_ + 255) / 256, 256>>>(ab_, attn_w);

    // Output projection
    sgemm_kernel<0, false><<<gI, 256>>>(ob_, Wo, bo, nullptr, attn_out, MI_, D_, D_);

    // Normalized similarity
    norm_kernel<<<B_, 256>>>(attn_out, pt, n1_, n2_);
    score_kernel<<<dim3(B_ / 16, B_ / 16), 256>>>(n1_, n2_, score);
}

// round 3
// speedup vs baseline: 1.5121x; 1.5121x over previous
#include <cuda_runtime.h>
#include <cuda_bf16.h>
#include <math.h>
#include <stdint.h>

// Problem dims
#define B_    512
#define SQ_   49
#define SK_   50
#define DIMG_ 2048
#define DTXT_ 768
#define D_    512
#define H_    4
#define DH_   128
#define MI_   (B_*SQ_)   // 25088
#define MT_   (B_*SK_)   // 25600

// ---------------------------------------------------------------------------
// Scratch (static __device__ — no allocations allowed)
// ---------------------------------------------------------------------------
__device__ __align__(256) float g_Pimg[MI_*D_];
__device__ __align__(256) float g_Ptxt[MT_*D_];
__device__ __align__(256) float g_q[MI_*D_];
__device__ __align__(256) float g_k[MT_*D_];
__device__ __align__(256) float g_v[MT_*D_];
__device__ __align__(256) float g_a[B_*H_*SQ_*SK_];
__device__ __align__(256) float g_o[MI_*D_];
__device__ __align__(256) float g_n1[B_*D_];
__device__ __align__(256) float g_n2[B_*D_];

// Transposed weights [N=512 rows][K cols], bf16 hi/lo, packed at offsets
#define WOFF_I1 0L
#define WOFF_T1 1048576L
#define WOFF_I2 1441792L
#define WOFF_T2 1703936L
#define WOFF_Q  1966080L
#define WOFF_K  2228224L
#define WOFF_V  2490368L
#define WOFF_O  2752512L
#define WTOT_   3014656L
__device__ __align__(256) __nv_bfloat16 g_Wth[WTOT_];
__device__ __align__(256) __nv_bfloat16 g_Wtl[WTOT_];

// ---------------------------------------------------------------------------
// Helpers
// ---------------------------------------------------------------------------
__device__ __forceinline__ uint32_t smem_u32(const void* p) {
    uint32_t a;
    asm("{ .reg .u64 t; cvta.to.shared.u64 t, %1; cvt.u32.u64 %0, t; }" : "=r"(a) : "l"(p));
    return a;
}
__device__ __forceinline__ void ldsm4(uint32_t* r, uint32_t addr) {
    asm volatile("ldmatrix.sync.aligned.m8n8.x4.shared.b16 {%0,%1,%2,%3}, [%4];"
        : "=r"(r[0]), "=r"(r[1]), "=r"(r[2]), "=r"(r[3]) : "r"(addr));
}
__device__ __forceinline__ void mma16816(float* d, const uint32_t* a, uint32_t b0, uint32_t b1) {
    asm volatile("mma.sync.aligned.m16n8k16.row.col.f32.bf16.bf16.f32 "
        "{%0,%1,%2,%3}, {%4,%5,%6,%7}, {%8,%9}, {%0,%1,%2,%3};"
        : "+f"(d[0]), "+f"(d[1]), "+f"(d[2]), "+f"(d[3])
        : "r"(a[0]), "r"(a[1]), "r"(a[2]), "r"(a[3]), "r"(b0), "r"(b1));
}
__device__ __forceinline__ void split2(float v, __nv_bfloat16& h, __nv_bfloat16& l) {
    h = __float2bfloat16_rn(v);
    l = __float2bfloat16_rn(v - __bfloat162float(h));
}
__device__ __forceinline__ uint32_t pk2(__nv_bfloat16 a, __nv_bfloat16 b) {
    unsigned short ra = *reinterpret_cast<unsigned short*>(&a);
    unsigned short rb = *reinterpret_cast<unsigned short*>(&b);
    return (uint32_t)ra | ((uint32_t)rb << 16);
}
__device__ __forceinline__ float gelu_f(float x) {
    return 0.5f * x * (1.0f + erff(x * 0.7071067811865476f));
}

// ---------------------------------------------------------------------------
// Split-bf16 tensor-core GEMM via mma.sync: C[M,512] = op(A)[M,K] @ W + bias (+Res)
// A: fp32 (split on the fly).  W: pre-split bf16 [512][K] hi/lo.
// ALOAD: 0 plain, 1 gelu-on-load, 2 image_features transposed layout.
// CTA 128x128, K-chunk 32, 8 warps (warp tile 64x32), double-buffered smem.
// Smem rows padded to 80B -> conflict-free ldmatrix.
// ---------------------------------------------------------------------------
#define STAGE_  40960
#define OFF_AH  0
#define OFF_AL  10240
#define OFF_BH  20480
#define OFF_BL  30720
#define SMEM_G  (2*STAGE_)

struct StReg {
    float4 a[4];
    float  a2[16];
    uint4  bh[2], bl[2];
};

template<int ALOAD>
__device__ __forceinline__ void g2r(StReg& r, const float* __restrict__ A,
    const __nv_bfloat16* __restrict__ Bh_, const __nv_bfloat16* __restrict__ Bl_,
    int m0, int n0, int K, int kt, int tid, const int* ifb)
{
    if (ALOAD == 2) {
        const int kq = tid & 31;
        #pragma unroll
        for (int j = 0; j < 16; j++)
            r.a2[j] = A[ifb[j] + (kt + kq) * SQ_];
    } else {
        #pragma unroll
        for (int i = 0; i < 4; i++) {
            const int c = tid + (i << 8);
            const int row = c >> 3, c8 = c & 7;
            r.a[i] = *reinterpret_cast<const float4*>(A + (long)(m0 + row) * K + kt + (c8 << 2));
        }
    }
    #pragma unroll
    for (int i = 0; i < 2; i++) {
        const int c = tid + (i << 8);
        const int row = c >> 2, c16 = c & 3;
        const long off = (long)(n0 + row) * K + kt + (c16 << 3);
        r.bh[i] = *reinterpret_cast<const uint4*>(Bh_ + off);
        r.bl[i] = *reinterpret_cast<const uint4*>(Bl_ + off);
    }
}

template<int ALOAD>
__device__ __forceinline__ void r2s(const StReg& r, char* buf, int tid)
{
    if (ALOAD == 2) {
        const int kq = tid & 31;
        const int mg = (tid >> 5) << 4;
        #pragma unroll
        for (int j = 0; j < 16; j++) {
            __nv_bfloat16 h, l; split2(r.a2[j], h, l);
            const int ro = (mg + j) * 80 + kq * 2;
            *reinterpret_cast<__nv_bfloat16*>(buf + OFF_AH + ro) = h;
            *reinterpret_cast<__nv_bfloat16*>(buf + OFF_AL + ro) = l;
        }
    } else {
        #pragma unroll
        for (int i = 0; i < 4; i++) {
            const int c = tid + (i << 8);
            const int row = c >> 3, c8 = c & 7;
            float4 v = r.a[i];
            if (ALOAD == 1) { v.x = gelu_f(v.x); v.y = gelu_f(v.y); v.z = gelu_f(v.z); v.w = gelu_f(v.w); }
            __nv_bfloat16 h0,h1,h2,h3,l0,l1,l2,l3;
            split2(v.x,h0,l0); split2(v.y,h1,l1); split2(v.z,h2,l2); split2(v.w,h3,l3);
            const int ro = row * 80 + (c8 << 3);
            *reinterpret_cast<uint2*>(buf + OFF_AH + ro) = make_uint2(pk2(h0,h1), pk2(h2,h3));
            *reinterpret_cast<uint2*>(buf + OFF_AL + ro) = make_uint2(pk2(l0,l1), pk2(l2,l3));
        }
    }
    #pragma unroll
    for (int i = 0; i < 2; i++) {
        const int c = tid + (i << 8);
        const int row = c >> 2, c16 = c & 3;
        const int ro = row * 80 + (c16 << 4);
        *reinterpret_cast<uint4*>(buf + OFF_BH + ro) = r.bh[i];
        *reinterpret_cast<uint4*>(buf + OFF_BL + ro) = r.bl[i];
    }
}

__device__ __forceinline__ void compute_chunk(uint32_t sb, int wid, int lane, float acc[4][4][4])
{
    const int wm = (wid & 1) << 6;
    const int wn = (wid >> 1) << 5;
    #pragma unroll
    for (int ks = 0; ks < 2; ks++) {
        uint32_t bhf[2][4], blf[2][4];
        #pragma unroll
        for (int p = 0; p < 2; p++) {
            const int row = wn + (p << 4) + (lane & 7) + (((lane >> 4) & 1) << 3);
            const int cb  = (lane >> 3) & 1;
            const uint32_t ad = sb + OFF_BH + row * 80 + (ks << 5) + (cb << 4);
            ldsm4(bhf[p], ad);
            ldsm4(blf[p], ad + (OFF_BL - OFF_BH));
        }
        #pragma unroll
        for (int mt = 0; mt < 4; mt++) {
            const int row = wm + (mt << 4) + (lane & 15);
            const int cb  = lane >> 4;
            const uint32_t ad = sb + OFF_AH + row * 80 + (ks << 5) + (cb << 4);
            uint32_t ahf[4], alf[4];
            ldsm4(ahf, ad);
            ldsm4(alf, ad + (OFF_AL - OFF_AH));
            #pragma unroll
            for (int nt2 = 0; nt2 < 4; nt2++) {
                const uint32_t b0h = bhf[nt2 >> 1][(nt2 & 1) << 1];
                const uint32_t b1h = bhf[nt2 >> 1][((nt2 & 1) << 1) + 1];
                const uint32_t b0l = blf[nt2 >> 1][(nt2 & 1) << 1];
                const uint32_t b1l = blf[nt2 >> 1][((nt2 & 1) << 1) + 1];
                mma16816(acc[mt][nt2], ahf, b0h, b1h);
                mma16816(acc[mt][nt2], ahf, b0l, b1l);
                mma16816(acc[mt][nt2], alf, b0h, b1h);
            }
        }
    }
}

template<int ALOAD, bool RES>
__global__ __launch_bounds__(256, 1) void mma_gemm_kernel(
    const float* __restrict__ A,
    const __nv_bfloat16* __restrict__ Bh_, const __nv_bfloat16* __restrict__ Bl_,
    const float* __restrict__ bias, const float* __restrict__ Res,
    float* __restrict__ C, int K)
{
    extern __shared__ __align__(16) char smem[];
    const uint32_t sbase = smem_u32(smem);
    const int tid  = threadIdx.x;
    const int wid  = tid >> 5;
    const int lane = tid & 31;
    const int m0 = blockIdx.y * 128;
    const int n0 = blockIdx.x * 128;

    int ifb[16];
    if (ALOAD == 2) {
        const int mg = (tid >> 5) << 4;
        #pragma unroll
        for (int j = 0; j < 16; j++) {
            const int m = m0 + mg + j;
            const int bb = m / SQ_;
            const int qq = m - bb * SQ_;
            ifb[j] = bb * (DIMG_ * SQ_) + qq;
        }
    }

    float acc[4][4][4];
    #pragma unroll
    for (int i = 0; i < 4; i++)
        #pragma unroll
        for (int j = 0; j < 4; j++)
            #pragma unroll
            for (int k = 0; k < 4; k++) acc[i][j][k] = 0.f;

    const int nt = K >> 5;
    StReg r;
    g2r<ALOAD>(r, A, Bh_, Bl_, m0, n0, K, 0, tid, ifb);
    r2s<ALOAD>(r, smem, tid);
    __syncthreads();

    for (int t = 0; t < nt; t++) {
        const int cur = t & 1;
        if (t + 1 < nt)
            g2r<ALOAD>(r, A, Bh_, Bl_, m0, n0, K, (t + 1) << 5, tid, ifb);
        compute_chunk(sbase + cur * STAGE_, wid, lane, acc);
        if (t + 1 < nt)
            r2s<ALOAD>(r, smem + (cur ^ 1) * STAGE_, tid);
        __syncthreads();
    }

    // Epilogue
    const int wm = (wid & 1) << 6;
    const int wn = (wid >> 1) << 5;
    #pragma unroll
    for (int mt = 0; mt < 4; mt++) {
        const int r0 = m0 + wm + (mt << 4) + (lane >> 2);
        #pragma unroll
        for (int nt2 = 0; nt2 < 4; nt2++) {
            const int cc = n0 + wn + (nt2 << 3) + ((lane & 3) << 1);
            const float2 bv = *reinterpret_cast<const float2*>(bias + cc);
            float2 o0, o1;
            o0.x = acc[mt][nt2][0] + bv.x; o0.y = acc[mt][nt2][1] + bv.y;
            o1.x = acc[mt][nt2][2] + bv.x; o1.y = acc[mt][nt2][3] + bv.y;
            if (RES) {
                const float2 r0v = *reinterpret_cast<const float2*>(Res + (long)r0 * D_ + cc);
                const float2 r1v = *reinterpret_cast<const float2*>(Res + (long)(r0 + 8) * D_ + cc);
                o0.x += r0v.x; o0.y += r0v.y; o1.x += r1v.x; o1.y += r1v.y;
            }
            *reinterpret_cast<float2*>(C + (long)r0 * D_ + cc)       = o0;
            *reinterpret_cast<float2*>(C + (long)(r0 + 8) * D_ + cc) = o1;
        }
    }
}

// ---------------------------------------------------------------------------
// Weight transpose+split: W [K, 512] -> Wt[n][k] bf16 hi/lo
// ---------------------------------------------------------------------------
__global__ __launch_bounds__(256) void wt_split_kernel(const float* __restrict__ W,
    __nv_bfloat16* __restrict__ th, __nv_bfloat16* __restrict__ tl, int K) {
    __shared__ float sm[32][33];
    const int k0 = blockIdx.x * 32;
    const int n0 = blockIdx.y * 32;
    for (int i = threadIdx.x; i < 1024; i += 256) {
        int r = i >> 5, c = i & 31;
        sm[r][c] = W[(long)(k0 + r) * D_ + n0 + c];
    }
    __syncthreads();
    for (int i = threadIdx.x; i < 1024; i += 256) {
        int r = i >> 5, c = i & 31;
        __nv_bfloat16 hb, lb; split2(sm[c][r], hb, lb);
        long o = (long)(n0 + r) * K + k0 + c;
        th[o] = hb; tl[o] = lb;
    }
}

// ---------------------------------------------------------------------------
// LayerNorm (in-place over last dim 512)
// ---------------------------------------------------------------------------
__global__ __launch_bounds__(128) void ln_kernel(
    float* __restrict__ X, const float* __restrict__ g, const float* __restrict__ be)
{
    const long row = blockIdx.x;
    float* xr = X + row * D_;
    const int t = threadIdx.x;
    float4 v = *reinterpret_cast<const float4*>(xr + t * 4);
    float s  = v.x + v.y + v.z + v.w;
    float sq = v.x*v.x + v.y*v.y + v.z*v.z + v.w*v.w;
    #pragma unroll
    for (int o = 16; o; o >>= 1) {
        s  += __shfl_xor_sync(0xffffffffu, s,  o);
        sq += __shfl_xor_sync(0xffffffffu, sq, o);
    }
    __shared__ float sh[8];
    if ((t & 31) == 0) { sh[t >> 5] = s; sh[4 + (t >> 5)] = sq; }
    __syncthreads();
    const float ts = sh[0] + sh[1] + sh[2] + sh[3];
    const float tq = sh[4] + sh[5] + sh[6] + sh[7];
    const float mu  = ts * (1.f / 512.f);
    const float var = tq * (1.f / 512.f) - mu * mu;
    const float inv = rsqrtf(var + 1e-5f);
    float4 gv = *reinterpret_cast<const float4*>(g  + t * 4);
    float4 bv = *reinterpret_cast<const float4*>(be + t * 4);
    v.x = gv.x * (v.x - mu) * inv + bv.x;
    v.y = gv.y * (v.y - mu) * inv + bv.y;
    v.z = gv.z * (v.z - mu) * inv + bv.z;
    v.w = gv.w * (v.w - mu) * inv + bv.w;
    *reinterpret_cast<float4*>(xr + t * 4) = v;
}

// ---------------------------------------------------------------------------
// Attention per (b,h)
// ---------------------------------------------------------------------------
__global__ __launch_bounds__(256) void attn_kernel(
    const float* __restrict__ q, const float* __restrict__ k,
    const float* __restrict__ v, float* __restrict__ a, float* __restrict__ o)
{
    const int bh = blockIdx.x;
    const int b  = bh >> 2;
    const int h  = bh & 3;
    __shared__ float kv[SK_ * DH_];
    __shared__ float s[SQ_ * SK_];
    const int tid = threadIdx.x;

    const float* kb = k + (long)b * SK_ * D_ + h * DH_;
    for (int i = tid; i < SK_ * DH_; i += 256) {
        int r = i >> 7, d = i & 127;
        kv[i] = kb[(long)r * D_ + d];
    }
    __syncthreads();

    const float* qb = q + (long)b * SQ_ * D_ + h * DH_;
    for (int i = tid; i < SQ_ * SK_; i += 256) {
        int qi = i / SK_, ki = i - qi * SK_;
        const float* qr = qb + (long)qi * D_;
        const float* kr = kv + ki * DH_;
        float accv = 0.f;
        #pragma unroll 8
        for (int d = 0; d < DH_; d++) accv += qr[d] * kr[d];
        s[i] = accv * 0.08838834764831845f;
    }
    __syncthreads();

    const float* vb = v + (long)b * SK_ * D_ + h * DH_;
    for (int i = tid; i < SK_ * DH_; i += 256) {
        int r = i >> 7, d = i & 127;
        kv[i] = vb[(long)r * D_ + d];
    }
    const int w = tid >> 5, lane = tid & 31;
    for (int row = w; row < SQ_; row += 8) {
        float mx = -1e30f;
        for (int c = lane; c < SK_; c += 32) mx = fmaxf(mx, s[row * SK_ + c]);
        #pragma unroll
        for (int off = 16; off; off >>= 1) mx = fmaxf(mx, __shfl_xor_sync(0xffffffffu, mx, off));
        float sum = 0.f;
        for (int c = lane; c < SK_; c += 32) {
            float e = __expf(s[row * SK_ + c] - mx);
            s[row * SK_ + c] = e;
            sum += e;
        }
        #pragma unroll
        for (int off = 16; off; off >>= 1) sum += __shfl_xor_sync(0xffffffffu, sum, off);
        const float inv = 1.f / sum;
        float* arow = a + ((long)(b * H_ + h) * SQ_ + row) * SK_;
        for (int c = lane; c < SK_; c += 32) {
            float p = s[row * SK_ + c] * inv;
            s[row * SK_ + c] = p;
            arow[c] = p;
        }
    }
    __syncthreads();

    float* ob = o + (long)b * SQ_ * D_ + h * DH_;
    for (int i = tid; i < SQ_ * DH_; i += 256) {
        int qi = i >> 7, d = i & 127;
        const float* sr = s + qi * SK_;
        float accv = 0.f;
        #pragma unroll
        for (int kk = 0; kk < SK_; kk++) accv += sr[kk] * kv[kk * DH_ + d];
        ob[(long)qi * D_ + d] = accv;
    }
}

__global__ void meanh_kernel(const float* __restrict__ a, float* __restrict__ out)
{
    const int idx = blockIdx.x * 256 + threadIdx.x;
    if (idx >= B_ * SQ_ * SK_) return;
    const int b = idx / (SQ_ * SK_);
    const int r = idx - b * (SQ_ * SK_);
    float sum = 0.f;
    #pragma unroll
    for (int h = 0; h < H_; h++)
        sum += a[((long)(b * H_ + h)) * (SQ_ * SK_) + r];
    out[idx] = sum * 0.25f;
}

__global__ __launch_bounds__(256) void norm_kernel(
    const float* __restrict__ ao, const float* __restrict__ pt,
    float* __restrict__ n1, float* __restrict__ n2)
{
    const int b = blockIdx.x;
    const int t = threadIdx.x;
    float v1[2], v2[2];
    float sq1 = 0.f, sq2 = 0.f;
    #pragma unroll
    for (int j = 0; j < 2; j++) {
        const int d = t + j * 256;
        const float* base = ao + (long)b * SQ_ * D_ + d;
        float sum = 0.f;
        #pragma unroll
        for (int qq = 0; qq < SQ_; qq++) sum += base[(long)qq * D_];
        sum *= (1.f / 49.f);
        v1[j] = sum; sq1 += sum * sum;
        const float c = pt[(long)b * SK_ * D_ + d];
        v2[j] = c; sq2 += c * c;
    }
    #pragma unroll
    for (int o = 16; o; o >>= 1) {
        sq1 += __shfl_xor_sync(0xffffffffu, sq1, o);
        sq2 += __shfl_xor_sync(0xffffffffu, sq2, o);
    }
    __shared__ float s1[8], s2[8];
    if ((t & 31) == 0) { s1[t >> 5] = sq1; s2[t >> 5] = sq2; }
    __syncthreads();
    float t1 = 0.f, t2 = 0.f;
    #pragma unroll
    for (int i = 0; i < 8; i++) { t1 += s1[i]; t2 += s2[i]; }
    const float i1 = rsqrtf(t1), i2 = rsqrtf(t2);
    #pragma unroll
    for (int j = 0; j < 2; j++) {
        const int d = t + j * 256;
        n1[(long)b * D_ + d] = v1[j] * i1;
        n2[(long)b * D_ + d] = v2[j] * i2;
    }
}

__global__ __launch_bounds__(256) void score_kernel(
    const float* __restrict__ n1, const float* __restrict__ n2, float* __restrict__ out)
{
    __shared__ float As[16][17];
    __shared__ float Bs[16][17];
    const int tx = threadIdx.x & 15;
    const int ty = threadIdx.x >> 4;
    const int i0 = blockIdx.y * 16;
    const int j0 = blockIdx.x * 16;
    float acc = 0.f;
    for (int k0 = 0; k0 < D_; k0 += 16) {
        As[ty][tx] = n1[(long)(i0 + ty) * D_ + k0 + tx];
        Bs[ty][tx] = n2[(long)(j0 + ty) * D_ + k0 + tx];
        __syncthreads();
        #pragma unroll
        for (int e = 0; e < 16; e++) acc += As[ty][e] * Bs[tx][e];
        __syncthreads();
    }
    out[(long)(i0 + ty) * B_ + j0 + tx] = acc;
}

// ---------------------------------------------------------------------------
extern "C" void kernel_launch(void* const* d_in, const int* in_sizes, int n_in,
                              void* d_out, int out_size)
{
    (void)in_sizes; (void)n_in; (void)out_size;
    const float* IF  = (const float*)d_in[0];
    const float* TXT = (const float*)d_in[1];
    const float* Wi1 = (const float*)d_in[2];
    const float* bi1 = (const float*)d_in[3];
    const float* Wi2 = (const float*)d_in[4];
    const float* bi2 = (const float*)d_in[5];
    const float* gi  = (const float*)d_in[6];
    const float* bei = (const float*)d_in[7];
    const float* Wt1 = (const float*)d_in[8];
    const float* bt1 = (const float*)d_in[9];
    const float* Wt2 = (const float*)d_in[10];
    const float* bt2 = (const float*)d_in[11];
    const float* gt  = (const float*)d_in[12];
    const float* bet = (const float*)d_in[13];
    const float* Wq  = (const float*)d_in[14];
    const float* bq  = (const float*)d_in[15];
    const float* Wk  = (const float*)d_in[16];
    const float* bk  = (const float*)d_in[17];
    const float* Wv  = (const float*)d_in[18];
    const float* bv  = (const float*)d_in[19];
    const float* Wo  = (const float*)d_in[20];
    const float* bo  = (const float*)d_in[21];

    float* out       = (float*)d_out;
    float* score     = out;
    float* attn_out  = score + (long)B_ * B_;
    float* attn_w    = attn_out + (long)MI_ * D_;
    float* pi        = attn_w + (long)B_ * SQ_ * SK_;
    float* pt        = pi + (long)MI_ * D_;

    float *Pimg, *Ptxt, *qb_, *kb_, *vb_, *ab_, *ob_, *n1_, *n2_;
    __nv_bfloat16 *Wth, *Wtl;
    cudaGetSymbolAddress((void**)&Pimg, g_Pimg);
    cudaGetSymbolAddress((void**)&Ptxt, g_Ptxt);
    cudaGetSymbolAddress((void**)&qb_,  g_q);
    cudaGetSymbolAddress((void**)&kb_,  g_k);
    cudaGetSymbolAddress((void**)&vb_,  g_v);
    cudaGetSymbolAddress((void**)&ab_,  g_a);
    cudaGetSymbolAddress((void**)&ob_,  g_o);
    cudaGetSymbolAddress((void**)&n1_,  g_n1);
    cudaGetSymbolAddress((void**)&n2_,  g_n2);
    cudaGetSymbolAddress((void**)&Wth,  g_Wth);
    cudaGetSymbolAddress((void**)&Wtl,  g_Wtl);

    cudaFuncSetAttribute(mma_gemm_kernel<0,false>, cudaFuncAttributeMaxDynamicSharedMemorySize, SMEM_G);
    cudaFuncSetAttribute(mma_gemm_kernel<1,true>,  cudaFuncAttributeMaxDynamicSharedMemorySize, SMEM_G);
    cudaFuncSetAttribute(mma_gemm_kernel<2,false>, cudaFuncAttributeMaxDynamicSharedMemorySize, SMEM_G);

    const dim3 gI(4, MI_ / 128);   // (4, 196)
    const dim3 gT(4, MT_ / 128);   // (4, 200)

    // Weight transpose+split (bf16 hi/lo)
    wt_split_kernel<<<dim3(DIMG_/32, 16), 256>>>(Wi1, Wth + WOFF_I1, Wtl + WOFF_I1, DIMG_);
    wt_split_kernel<<<dim3(DTXT_/32, 16), 256>>>(Wt1, Wth + WOFF_T1, Wtl + WOFF_T1, DTXT_);
    wt_split_kernel<<<dim3(D_/32, 16), 256>>>(Wi2, Wth + WOFF_I2, Wtl + WOFF_I2, D_);
    wt_split_kernel<<<dim3(D_/32, 16), 256>>>(Wt2, Wth + WOFF_T2, Wtl + WOFF_T2, D_);
    wt_split_kernel<<<dim3(D_/32, 16), 256>>>(Wq,  Wth + WOFF_Q,  Wtl + WOFF_Q,  D_);
    wt_split_kernel<<<dim3(D_/32, 16), 256>>>(Wk,  Wth + WOFF_K,  Wtl + WOFF_K,  D_);
    wt_split_kernel<<<dim3(D_/32, 16), 256>>>(Wv,  Wth + WOFF_V,  Wtl + WOFF_V,  D_);
    wt_split_kernel<<<dim3(D_/32, 16), 256>>>(Wo,  Wth + WOFF_O,  Wtl + WOFF_O,  D_);

    // Image head
    mma_gemm_kernel<2,false><<<gI, 256, SMEM_G>>>(IF,   Wth+WOFF_I1, Wtl+WOFF_I1, bi1, nullptr, Pimg, DIMG_);
    mma_gemm_kernel<1,true ><<<gI, 256, SMEM_G>>>(Pimg, Wth+WOFF_I2, Wtl+WOFF_I2, bi2, Pimg,    pi,   D_);
    ln_kernel<<<MI_, 128>>>(pi, gi, bei);

    // Text head
    mma_gemm_kernel<0,false><<<gT, 256, SMEM_G>>>(TXT,  Wth+WOFF_T1, Wtl+WOFF_T1, bt1, nullptr, Ptxt, DTXT_);
    mma_gemm_kernel<1,true ><<<gT, 256, SMEM_G>>>(Ptxt, Wth+WOFF_T2, Wtl+WOFF_T2, bt2, Ptxt,    pt,   D_);
    ln_kernel<<<MT_, 128>>>(pt, gt, bet);

    // QKV
    mma_gemm_kernel<0,false><<<gI, 256, SMEM_G>>>(pi, Wth+WOFF_Q, Wtl+WOFF_Q, bq, nullptr, qb_, D_);
    mma_gemm_kernel<0,false><<<gT, 256, SMEM_G>>>(pt, Wth+WOFF_K, Wtl+WOFF_K, bk, nullptr, kb_, D_);
    mma_gemm_kernel<0,false><<<gT, 256, SMEM_G>>>(pt, Wth+WOFF_V, Wtl+WOFF_V, bv, nullptr, vb_, D_);

    // Attention
    attn_kernel<<<B_ * H_, 256>>>(qb_, kb_, vb_, ab_, ob_);
    meanh_kernel<<<(B_ * SQ_ * SK_ + 255) / 256, 256>>>(ab_, attn_w);

    // Output projection
    mma_gemm_kernel<0,false><<<gI, 256, SMEM_G>>>(ob_, Wth+WOFF_O, Wtl+WOFF_O, bo, nullptr, attn_out, D_);

    // Normalized similarity
    norm_kernel<<<B_, 256>>>(attn_out, pt, n1_, n2_);
    score_kernel<<<dim3(B_ / 16, B_ / 16), 256>>>(n1_, n2_, score);
}

// round 4
// speedup vs baseline: 1.5266x; 1.0096x over previous
#include <cuda_runtime.h>
#include <cuda_bf16.h>
#include <math.h>
#include <stdint.h>

// Problem dims
#define B_    512
#define SQ_   49
#define SK_   50
#define DIMG_ 2048
#define DTXT_ 768
#define D_    512
#define H_    4
#define DH_   128
#define MI_   (B_*SQ_)   // 25088
#define MT_   (B_*SK_)   // 25600

// ---------------------------------------------------------------------------
// Scratch (static __device__ — no allocations allowed)
// ---------------------------------------------------------------------------
__device__ __align__(256) float g_Pimg[MI_*D_];
__device__ __align__(256) float g_Ptxt[MT_*D_];
__device__ __align__(256) float g_q[MI_*D_];
__device__ __align__(256) float g_k[MT_*D_];
__device__ __align__(256) float g_v[MT_*D_];
__device__ __align__(256) float g_a[B_*H_*SQ_*SK_];
__device__ __align__(256) float g_o[MI_*D_];
__device__ __align__(256) float g_n1[B_*D_];
__device__ __align__(256) float g_n2[B_*D_];

// Activation bf16 hi/lo split buffers
#define AMAX_ (MI_*DIMG_)            // 51380224 elements (biggest A)
__device__ __align__(256) __nv_bfloat16 g_Ah[AMAX_];
__device__ __align__(256) __nv_bfloat16 g_Al[AMAX_];
__device__ __align__(256) __nv_bfloat16 g_pih[MI_*D_];
__device__ __align__(256) __nv_bfloat16 g_pil[MI_*D_];
__device__ __align__(256) __nv_bfloat16 g_pth[MT_*D_];
__device__ __align__(256) __nv_bfloat16 g_ptl[MT_*D_];

// Transposed weights [N=512 rows][K cols], bf16 hi/lo, packed at offsets
#define WOFF_I1 0L
#define WOFF_T1 1048576L
#define WOFF_I2 1441792L
#define WOFF_T2 1703936L
#define WOFF_Q  1966080L
#define WOFF_K  2228224L
#define WOFF_V  2490368L
#define WOFF_O  2752512L
#define WTOT_   3014656L
__device__ __align__(256) __nv_bfloat16 g_Wth[WTOT_];
__device__ __align__(256) __nv_bfloat16 g_Wtl[WTOT_];

// ---------------------------------------------------------------------------
// Helpers
// ---------------------------------------------------------------------------
__device__ __forceinline__ uint32_t smem_u32(const void* p) {
    uint32_t a;
    asm("{ .reg .u64 t; cvta.to.shared.u64 t, %1; cvt.u32.u64 %0, t; }" : "=r"(a) : "l"(p));
    return a;
}
__device__ __forceinline__ void ldsm4(uint32_t* r, uint32_t addr) {
    asm volatile("ldmatrix.sync.aligned.m8n8.x4.shared.b16 {%0,%1,%2,%3}, [%4];"
        : "=r"(r[0]), "=r"(r[1]), "=r"(r[2]), "=r"(r[3]) : "r"(addr));
}
__device__ __forceinline__ void mma16816(float* d, const uint32_t* a, uint32_t b0, uint32_t b1) {
    asm volatile("mma.sync.aligned.m16n8k16.row.col.f32.bf16.bf16.f32 "
        "{%0,%1,%2,%3}, {%4,%5,%6,%7}, {%8,%9}, {%0,%1,%2,%3};"
        : "+f"(d[0]), "+f"(d[1]), "+f"(d[2]), "+f"(d[3])
        : "r"(a[0]), "r"(a[1]), "r"(a[2]), "r"(a[3]), "r"(b0), "r"(b1));
}
__device__ __forceinline__ void cpa16(uint32_t s, const void* g) {
    asm volatile("cp.async.ca.shared.global [%0], [%1], 16;" :: "r"(s), "l"(g));
}
#define CPA_COMMIT() asm volatile("cp.async.commit_group;" ::: "memory")
#define CPA_WAIT0()  asm volatile("cp.async.wait_group 0;" ::: "memory")

__device__ __forceinline__ void split2(float v, __nv_bfloat16& h, __nv_bfloat16& l) {
    h = __float2bfloat16_rn(v);
    l = __float2bfloat16_rn(v - __bfloat162float(h));
}
__device__ __forceinline__ uint32_t pk2(__nv_bfloat16 a, __nv_bfloat16 b) {
    unsigned short ra = *reinterpret_cast<unsigned short*>(&a);
    unsigned short rb = *reinterpret_cast<unsigned short*>(&b);
    return (uint32_t)ra | ((uint32_t)rb << 16);
}
__device__ __forceinline__ float gelu_f(float x) {
    return 0.5f * x * (1.0f + erff(x * 0.7071067811865476f));
}

// ---------------------------------------------------------------------------
// Split conversion kernels (fp32 -> bf16 hi + lo), vectorized 4/thread
// ---------------------------------------------------------------------------
template<bool GELU>
__global__ __launch_bounds__(256) void split_kernel(const float* __restrict__ x,
    __nv_bfloat16* __restrict__ h, __nv_bfloat16* __restrict__ l, long n4)
{
    long i = (long)blockIdx.x * 256 + threadIdx.x;
    if (i >= n4) return;
    float4 v = reinterpret_cast<const float4*>(x)[i];
    if (GELU) { v.x = gelu_f(v.x); v.y = gelu_f(v.y); v.z = gelu_f(v.z); v.w = gelu_f(v.w); }
    __nv_bfloat16 h0,h1,h2,h3,l0,l1,l2,l3;
    split2(v.x,h0,l0); split2(v.y,h1,l1); split2(v.z,h2,l2); split2(v.w,h3,l3);
    reinterpret_cast<uint2*>(h)[i] = make_uint2(pk2(h0,h1), pk2(h2,h3));
    reinterpret_cast<uint2*>(l)[i] = make_uint2(pk2(l0,l1), pk2(l2,l3));
}

// image_features [B, DIMG, SQ] -> A[m=b*SQ+q][k] split
__global__ __launch_bounds__(256) void if_split_kernel(const float* __restrict__ IF,
    __nv_bfloat16* __restrict__ h, __nv_bfloat16* __restrict__ l) {
    __shared__ float sm[32][50];
    const int k0 = blockIdx.x * 32;
    const int b  = blockIdx.y;
    const float* base = IF + (long)b * DIMG_ * SQ_;
    for (int i = threadIdx.x; i < 32 * SQ_; i += 256) {
        int ky = i / SQ_, q = i - ky * SQ_;
        sm[ky][q] = base[(long)(k0 + ky) * SQ_ + q];
    }
    __syncthreads();
    for (int i = threadIdx.x; i < SQ_ * 32; i += 256) {
        int q = i >> 5, ky = i & 31;
        __nv_bfloat16 hb, lb; split2(sm[ky][q], hb, lb);
        long o = ((long)(b * SQ_ + q)) * DIMG_ + k0 + ky;
        h[o] = hb; l[o] = lb;
    }
}

// W [K, 512] -> Wt[n][k] bf16 hi/lo
__global__ __launch_bounds__(256) void wt_split_kernel(const float* __restrict__ W,
    __nv_bfloat16* __restrict__ th, __nv_bfloat16* __restrict__ tl, int K) {
    __shared__ float sm[32][33];
    const int k0 = blockIdx.x * 32;
    const int n0 = blockIdx.y * 32;
    for (int i = threadIdx.x; i < 1024; i += 256) {
        int r = i >> 5, c = i & 31;
        sm[r][c] = W[(long)(k0 + r) * D_ + n0 + c];
    }
    __syncthreads();
    for (int i = threadIdx.x; i < 1024; i += 256) {
        int r = i >> 5, c = i & 31;
        __nv_bfloat16 hb, lb; split2(sm[c][r], hb, lb);
        long o = (long)(n0 + r) * K + k0 + c;
        th[o] = hb; tl[o] = lb;
    }
}

// ---------------------------------------------------------------------------
// Split-bf16 tensor-core GEMM: C[M,512] = A @ W + bias (+Res)
// A: bf16 hi/lo [M,K].  W: bf16 hi/lo [512][K] (transposed).
// CTA 128x128, K-chunk 32, 8 warps (warp tile 64x32), cp.async double buffer.
// Smem rows padded to 80B -> conflict-free ldmatrix.
// ---------------------------------------------------------------------------
#define STAGE_  40960
#define OFF_AH  0
#define OFF_AL  10240
#define OFF_BH  20480
#define OFF_BL  30720
#define SMEM_G  (2*STAGE_)

__device__ __forceinline__ void stage_cp(uint32_t sb,
    const __nv_bfloat16* __restrict__ Ah, const __nv_bfloat16* __restrict__ Al,
    const __nv_bfloat16* __restrict__ Bh, const __nv_bfloat16* __restrict__ Bl,
    int m0, int n0, int K, int kt, int tid)
{
    #pragma unroll
    for (int i = 0; i < 2; i++) {
        const int idx = tid + (i << 8);      // 0..511
        const int row = idx >> 2, seg = idx & 3;
        const long ga = (long)(m0 + row) * K + kt + (seg << 3);
        const long gb = (long)(n0 + row) * K + kt + (seg << 3);
        const uint32_t so = row * 80 + (seg << 4);
        cpa16(sb + OFF_AH + so, Ah + ga);
        cpa16(sb + OFF_AL + so, Al + ga);
        cpa16(sb + OFF_BH + so, Bh + gb);
        cpa16(sb + OFF_BL + so, Bl + gb);
    }
}

__device__ __forceinline__ void compute_chunk(uint32_t sb, int wid, int lane, float acc[4][4][4])
{
    const int wm = (wid & 1) << 6;
    const int wn = (wid >> 1) << 5;
    #pragma unroll
    for (int ks = 0; ks < 2; ks++) {
        uint32_t bhf[2][4], blf[2][4];
        #pragma unroll
        for (int p = 0; p < 2; p++) {
            const int row = wn + (p << 4) + (lane & 7) + (((lane >> 4) & 1) << 3);
            const int cb  = (lane >> 3) & 1;
            const uint32_t ad = sb + OFF_BH + row * 80 + (ks << 5) + (cb << 4);
            ldsm4(bhf[p], ad);
            ldsm4(blf[p], ad + (OFF_BL - OFF_BH));
        }
        #pragma unroll
        for (int mt = 0; mt < 4; mt++) {
            const int row = wm + (mt << 4) + (lane & 15);
            const int cb  = lane >> 4;
            const uint32_t ad = sb + OFF_AH + row * 80 + (ks << 5) + (cb << 4);
            uint32_t ahf[4], alf[4];
            ldsm4(ahf, ad);
            ldsm4(alf, ad + (OFF_AL - OFF_AH));
            #pragma unroll
            for (int nt2 = 0; nt2 < 4; nt2++) {
                const uint32_t b0h = bhf[nt2 >> 1][(nt2 & 1) << 1];
                const uint32_t b1h = bhf[nt2 >> 1][((nt2 & 1) << 1) + 1];
                const uint32_t b0l = blf[nt2 >> 1][(nt2 & 1) << 1];
                const uint32_t b1l = blf[nt2 >> 1][((nt2 & 1) << 1) + 1];
                mma16816(acc[mt][nt2], ahf, b0h, b1h);
                mma16816(acc[mt][nt2], ahf, b0l, b1l);
                mma16816(acc[mt][nt2], alf, b0h, b1h);
            }
        }
    }
}

template<bool RES>
__global__ __launch_bounds__(256, 1) void mma_gemm_kernel(
    const __nv_bfloat16* __restrict__ Ah, const __nv_bfloat16* __restrict__ Al,
    const __nv_bfloat16* __restrict__ Bh_, const __nv_bfloat16* __restrict__ Bl_,
    const float* __restrict__ bias, const float* __restrict__ Res,
    float* __restrict__ C, int K)
{
    extern __shared__ __align__(16) char smem[];
    const uint32_t sbase = smem_u32(smem);
    const int tid  = threadIdx.x;
    const int wid  = tid >> 5;
    const int lane = tid & 31;
    const int m0 = blockIdx.y * 128;
    const int n0 = blockIdx.x * 128;

    float acc[4][4][4];
    #pragma unroll
    for (int i = 0; i < 4; i++)
        #pragma unroll
        for (int j = 0; j < 4; j++)
            #pragma unroll
            for (int k = 0; k < 4; k++) acc[i][j][k] = 0.f;

    const int nt = K >> 5;

    stage_cp(sbase, Ah, Al, Bh_, Bl_, m0, n0, K, 0, tid);
    CPA_COMMIT();

    for (int t = 0; t < nt; t++) {
        const int cur = t & 1;
        CPA_WAIT0();
        __syncthreads();
        if (t + 1 < nt) {
            stage_cp(sbase + (cur ^ 1) * STAGE_, Ah, Al, Bh_, Bl_, m0, n0, K, (t + 1) << 5, tid);
            CPA_COMMIT();
        }
        compute_chunk(sbase + cur * STAGE_, wid, lane, acc);
        __syncthreads();
    }

    // Epilogue
    const int wm = (wid & 1) << 6;
    const int wn = (wid >> 1) << 5;
    #pragma unroll
    for (int mt = 0; mt < 4; mt++) {
        const int r0 = m0 + wm + (mt << 4) + (lane >> 2);
        #pragma unroll
        for (int nt2 = 0; nt2 < 4; nt2++) {
            const int cc = n0 + wn + (nt2 << 3) + ((lane & 3) << 1);
            const float2 bv = *reinterpret_cast<const float2*>(bias + cc);
            float2 o0, o1;
            o0.x = acc[mt][nt2][0] + bv.x; o0.y = acc[mt][nt2][1] + bv.y;
            o1.x = acc[mt][nt2][2] + bv.x; o1.y = acc[mt][nt2][3] + bv.y;
            if (RES) {
                const float2 r0v = *reinterpret_cast<const float2*>(Res + (long)r0 * D_ + cc);
                const float2 r1v = *reinterpret_cast<const float2*>(Res + (long)(r0 + 8) * D_ + cc);
                o0.x += r0v.x; o0.y += r0v.y; o1.x += r1v.x; o1.y += r1v.y;
            }
            *reinterpret_cast<float2*>(C + (long)r0 * D_ + cc)       = o0;
            *reinterpret_cast<float2*>(C + (long)(r0 + 8) * D_ + cc) = o1;
        }
    }
}

// ---------------------------------------------------------------------------
// LayerNorm (in-place over last dim 512)
// ---------------------------------------------------------------------------
__global__ __launch_bounds__(128) void ln_kernel(
    float* __restrict__ X, const float* __restrict__ g, const float* __restrict__ be)
{
    const long row = blockIdx.x;
    float* xr = X + row * D_;
    const int t = threadIdx.x;
    float4 v = *reinterpret_cast<const float4*>(xr + t * 4);
    float s  = v.x + v.y + v.z + v.w;
    float sq = v.x*v.x + v.y*v.y + v.z*v.z + v.w*v.w;
    #pragma unroll
    for (int o = 16; o; o >>= 1) {
        s  += __shfl_xor_sync(0xffffffffu, s,  o);
        sq += __shfl_xor_sync(0xffffffffu, sq, o);
    }
    __shared__ float sh[8];
    if ((t & 31) == 0) { sh[t >> 5] = s; sh[4 + (t >> 5)] = sq; }
    __syncthreads();
    const float ts = sh[0] + sh[1] + sh[2] + sh[3];
    const float tq = sh[4] + sh[5] + sh[6] + sh[7];
    const float mu  = ts * (1.f / 512.f);
    const float var = tq * (1.f / 512.f) - mu * mu;
    const float inv = rsqrtf(var + 1e-5f);
    float4 gv = *reinterpret_cast<const float4*>(g  + t * 4);
    float4 bv = *reinterpret_cast<const float4*>(be + t * 4);
    v.x = gv.x * (v.x - mu) * inv + bv.x;
    v.y = gv.y * (v.y - mu) * inv + bv.y;
    v.z = gv.z * (v.z - mu) * inv + bv.z;
    v.w = gv.w * (v.w - mu) * inv + bv.w;
    *reinterpret_cast<float4*>(xr + t * 4) = v;
}

// ---------------------------------------------------------------------------
// Attention per (b,h)
// ---------------------------------------------------------------------------
__global__ __launch_bounds__(256) void attn_kernel(
    const float* __restrict__ q, const float* __restrict__ k,
    const float* __restrict__ v, float* __restrict__ a, float* __restrict__ o)
{
    const int bh = blockIdx.x;
    const int b  = bh >> 2;
    const int h  = bh & 3;
    __shared__ float kv[SK_ * DH_];
    __shared__ float s[SQ_ * SK_];
    const int tid = threadIdx.x;

    const float* kb = k + (long)b * SK_ * D_ + h * DH_;
    for (int i = tid; i < SK_ * DH_; i += 256) {
        int r = i >> 7, d = i & 127;
        kv[i] = kb[(long)r * D_ + d];
    }
    __syncthreads();

    const float* qb = q + (long)b * SQ_ * D_ + h * DH_;
    for (int i = tid; i < SQ_ * SK_; i += 256) {
        int qi = i / SK_, ki = i - qi * SK_;
        const float* qr = qb + (long)qi * D_;
        const float* kr = kv + ki * DH_;
        float accv = 0.f;
        #pragma unroll 8
        for (int d = 0; d < DH_; d++) accv += qr[d] * kr[d];
        s[i] = accv * 0.08838834764831845f;
    }
    __syncthreads();

    const float* vb = v + (long)b * SK_ * D_ + h * DH_;
    for (int i = tid; i < SK_ * DH_; i += 256) {
        int r = i >> 7, d = i & 127;
        kv[i] = vb[(long)r * D_ + d];
    }
    const int w = tid >> 5, lane = tid & 31;
    for (int row = w; row < SQ_; row += 8) {
        float mx = -1e30f;
        for (int c = lane; c < SK_; c += 32) mx = fmaxf(mx, s[row * SK_ + c]);
        #pragma unroll
        for (int off = 16; off; off >>= 1) mx = fmaxf(mx, __shfl_xor_sync(0xffffffffu, mx, off));
        float sum = 0.f;
        for (int c = lane; c < SK_; c += 32) {
            float e = __expf(s[row * SK_ + c] - mx);
            s[row * SK_ + c] = e;
            sum += e;
        }
        #pragma unroll
        for (int off = 16; off; off >>= 1) sum += __shfl_xor_sync(0xffffffffu, sum, off);
        const float inv = 1.f / sum;
        float* arow = a + ((long)(b * H_ + h) * SQ_ + row) * SK_;
        for (int c = lane; c < SK_; c += 32) {
            float p = s[row * SK_ + c] * inv;
            s[row * SK_ + c] = p;
            arow[c] = p;
        }
    }
    __syncthreads();

    float* ob = o + (long)b * SQ_ * D_ + h * DH_;
    for (int i = tid; i < SQ_ * DH_; i += 256) {
        int qi = i >> 7, d = i & 127;
        const float* sr = s + qi * SK_;
        float accv = 0.f;
        #pragma unroll
        for (int kk = 0; kk < SK_; kk++) accv += sr[kk] * kv[kk * DH_ + d];
        ob[(long)qi * D_ + d] = accv;
    }
}

__global__ void meanh_kernel(const float* __restrict__ a, float* __restrict__ out)
{
    const int idx = blockIdx.x * 256 + threadIdx.x;
    if (idx >= B_ * SQ_ * SK_) return;
    const int b = idx / (SQ_ * SK_);
    const int r = idx - b * (SQ_ * SK_);
    float sum = 0.f;
    #pragma unroll
    for (int h = 0; h < H_; h++)
        sum += a[((long)(b * H_ + h)) * (SQ_ * SK_) + r];
    out[idx] = sum * 0.25f;
}

__global__ __launch_bounds__(256) void norm_kernel(
    const float* __restrict__ ao, const float* __restrict__ pt,
    float* __restrict__ n1, float* __restrict__ n2)
{
    const int b = blockIdx.x;
    const int t = threadIdx.x;
    float v1[2], v2[2];
    float sq1 = 0.f, sq2 = 0.f;
    #pragma unroll
    for (int j = 0; j < 2; j++) {
        const int d = t + j * 256;
        const float* base = ao + (long)b * SQ_ * D_ + d;
        float sum = 0.f;
        #pragma unroll
        for (int qq = 0; qq < SQ_; qq++) sum += base[(long)qq * D_];
        sum *= (1.f / 49.f);
        v1[j] = sum; sq1 += sum * sum;
        const float c = pt[(long)b * SK_ * D_ + d];
        v2[j] = c; sq2 += c * c;
    }
    #pragma unroll
    for (int o = 16; o; o >>= 1) {
        sq1 += __shfl_xor_sync(0xffffffffu, sq1, o);
        sq2 += __shfl_xor_sync(0xffffffffu, sq2, o);
    }
    __shared__ float s1[8], s2[8];
    if ((t & 31) == 0) { s1[t >> 5] = sq1; s2[t >> 5] = sq2; }
    __syncthreads();
    float t1 = 0.f, t2 = 0.f;
    #pragma unroll
    for (int i = 0; i < 8; i++) { t1 += s1[i]; t2 += s2[i]; }
    const float i1 = rsqrtf(t1), i2 = rsqrtf(t2);
    #pragma unroll
    for (int j = 0; j < 2; j++) {
        const int d = t + j * 256;
        n1[(long)b * D_ + d] = v1[j] * i1;
        n2[(long)b * D_ + d] = v2[j] * i2;
    }
}

__global__ __launch_bounds__(256) void score_kernel(
    const float* __restrict__ n1, const float* __restrict__ n2, float* __restrict__ out)
{
    __shared__ float As[16][17];
    __shared__ float Bs[16][17];
    const int tx = threadIdx.x & 15;
    const int ty = threadIdx.x >> 4;
    const int i0 = blockIdx.y * 16;
    const int j0 = blockIdx.x * 16;
    float acc = 0.f;
    for (int k0 = 0; k0 < D_; k0 += 16) {
        As[ty][tx] = n1[(long)(i0 + ty) * D_ + k0 + tx];
        Bs[ty][tx] = n2[(long)(j0 + ty) * D_ + k0 + tx];
        __syncthreads();
        #pragma unroll
        for (int e = 0; e < 16; e++) acc += As[ty][e] * Bs[tx][e];
        __syncthreads();
    }
    out[(long)(i0 + ty) * B_ + j0 + tx] = acc;
}

// ---------------------------------------------------------------------------
extern "C" void kernel_launch(void* const* d_in, const int* in_sizes, int n_in,
                              void* d_out, int out_size)
{
    (void)in_sizes; (void)n_in; (void)out_size;
    const float* IF  = (const float*)d_in[0];
    const float* TXT = (const float*)d_in[1];
    const float* Wi1 = (const float*)d_in[2];
    const float* bi1 = (const float*)d_in[3];
    const float* Wi2 = (const float*)d_in[4];
    const float* bi2 = (const float*)d_in[5];
    const float* gi  = (const float*)d_in[6];
    const float* bei = (const float*)d_in[7];
    const float* Wt1 = (const float*)d_in[8];
    const float* bt1 = (const float*)d_in[9];
    const float* Wt2 = (const float*)d_in[10];
    const float* bt2 = (const float*)d_in[11];
    const float* gt  = (const float*)d_in[12];
    const float* bet = (const float*)d_in[13];
    const float* Wq  = (const float*)d_in[14];
    const float* bq  = (const float*)d_in[15];
    const float* Wk  = (const float*)d_in[16];
    const float* bk  = (const float*)d_in[17];
    const float* Wv  = (const float*)d_in[18];
    const float* bv  = (const float*)d_in[19];
    const float* Wo  = (const float*)d_in[20];
    const float* bo  = (const float*)d_in[21];

    float* out       = (float*)d_out;
    float* score     = out;
    float* attn_out  = score + (long)B_ * B_;
    float* attn_w    = attn_out + (long)MI_ * D_;
    float* pi        = attn_w + (long)B_ * SQ_ * SK_;
    float* pt        = pi + (long)MI_ * D_;

    float *Pimg, *Ptxt, *qb_, *kb_, *vb_, *ab_, *ob_, *n1_, *n2_;
    __nv_bfloat16 *Ah, *Al, *pih, *pil, *pth, *ptl, *Wth, *Wtl;
    cudaGetSymbolAddress((void**)&Pimg, g_Pimg);
    cudaGetSymbolAddress((void**)&Ptxt, g_Ptxt);
    cudaGetSymbolAddress((void**)&qb_,  g_q);
    cudaGetSymbolAddress((void**)&kb_,  g_k);
    cudaGetSymbolAddress((void**)&vb_,  g_v);
    cudaGetSymbolAddress((void**)&ab_,  g_a);
    cudaGetSymbolAddress((void**)&ob_,  g_o);
    cudaGetSymbolAddress((void**)&n1_,  g_n1);
    cudaGetSymbolAddress((void**)&n2_,  g_n2);
    cudaGetSymbolAddress((void**)&Ah,   g_Ah);
    cudaGetSymbolAddress((void**)&Al,   g_Al);
    cudaGetSymbolAddress((void**)&pih,  g_pih);
    cudaGetSymbolAddress((void**)&pil,  g_pil);
    cudaGetSymbolAddress((void**)&pth,  g_pth);
    cudaGetSymbolAddress((void**)&ptl,  g_ptl);
    cudaGetSymbolAddress((void**)&Wth,  g_Wth);
    cudaGetSymbolAddress((void**)&Wtl,  g_Wtl);

    cudaFuncSetAttribute(mma_gemm_kernel<false>, cudaFuncAttributeMaxDynamicSharedMemorySize, SMEM_G);
    cudaFuncSetAttribute(mma_gemm_kernel<true>,  cudaFuncAttributeMaxDynamicSharedMemorySize, SMEM_G);

    const dim3 gI(4, MI_ / 128);   // (4, 196)
    const dim3 gT(4, MT_ / 128);   // (4, 200)

    // Weight transpose+split (bf16 hi/lo)
    wt_split_kernel<<<dim3(DIMG_/32, 16), 256>>>(Wi1, Wth + WOFF_I1, Wtl + WOFF_I1, DIMG_);
    wt_split_kernel<<<dim3(DTXT_/32, 16), 256>>>(Wt1, Wth + WOFF_T1, Wtl + WOFF_T1, DTXT_);
    wt_split_kernel<<<dim3(D_/32, 16), 256>>>(Wi2, Wth + WOFF_I2, Wtl + WOFF_I2, D_);
    wt_split_kernel<<<dim3(D_/32, 16), 256>>>(Wt2, Wth + WOFF_T2, Wtl + WOFF_T2, D_);
    wt_split_kernel<<<dim3(D_/32, 16), 256>>>(Wq,  Wth + WOFF_Q,  Wtl + WOFF_Q,  D_);
    wt_split_kernel<<<dim3(D_/32, 16), 256>>>(Wk,  Wth + WOFF_K,  Wtl + WOFF_K,  D_);
    wt_split_kernel<<<dim3(D_/32, 16), 256>>>(Wv,  Wth + WOFF_V,  Wtl + WOFF_V,  D_);
    wt_split_kernel<<<dim3(D_/32, 16), 256>>>(Wo,  Wth + WOFF_O,  Wtl + WOFF_O,  D_);

    // Image head
    if_split_kernel<<<dim3(DIMG_/32, B_), 256>>>(IF, Ah, Al);
    mma_gemm_kernel<false><<<gI, 256, SMEM_G>>>(Ah, Al, Wth+WOFF_I1, Wtl+WOFF_I1, bi1, nullptr, Pimg, DIMG_);
    split_kernel<true ><<<((long)MI_*D_/4 + 255)/256, 256>>>(Pimg, Ah, Al, (long)MI_*D_/4);
    mma_gemm_kernel<true ><<<gI, 256, SMEM_G>>>(Ah, Al, Wth+WOFF_I2, Wtl+WOFF_I2, bi2, Pimg, pi, D_);
    ln_kernel<<<MI_, 128>>>(pi, gi, bei);

    // Text head
    split_kernel<false><<<((long)MT_*DTXT_/4 + 255)/256, 256>>>(TXT, Ah, Al, (long)MT_*DTXT_/4);
    mma_gemm_kernel<false><<<gT, 256, SMEM_G>>>(Ah, Al, Wth+WOFF_T1, Wtl+WOFF_T1, bt1, nullptr, Ptxt, DTXT_);
    split_kernel<true ><<<((long)MT_*D_/4 + 255)/256, 256>>>(Ptxt, Ah, Al, (long)MT_*D_/4);
    mma_gemm_kernel<true ><<<gT, 256, SMEM_G>>>(Ah, Al, Wth+WOFF_T2, Wtl+WOFF_T2, bt2, Ptxt, pt, D_);
    ln_kernel<<<MT_, 128>>>(pt, gt, bet);

    // QKV
    split_kernel<false><<<((long)MI_*D_/4 + 255)/256, 256>>>(pi, pih, pil, (long)MI_*D_/4);
    split_kernel<false><<<((long)MT_*D_/4 + 255)/256, 256>>>(pt, pth, ptl, (long)MT_*D_/4);
    mma_gemm_kernel<false><<<gI, 256, SMEM_G>>>(pih, pil, Wth+WOFF_Q, Wtl+WOFF_Q, bq, nullptr, qb_, D_);
    mma_gemm_kernel<false><<<gT, 256, SMEM_G>>>(pth, ptl, Wth+WOFF_K, Wtl+WOFF_K, bk, nullptr, kb_, D_);
    mma_gemm_kernel<false><<<gT, 256, SMEM_G>>>(pth, ptl, Wth+WOFF_V, Wtl+WOFF_V, bv, nullptr, vb_, D_);

    // Attention
    attn_kernel<<<B_ * H_, 256>>>(qb_, kb_, vb_, ab_, ob_);
    meanh_kernel<<<(B_ * SQ_ * SK_ + 255) / 256, 256>>>(ab_, attn_w);

    // Output projection
    split_kernel<false><<<((long)MI_*D_/4 + 255)/256, 256>>>(ob_, Ah, Al, (long)MI_*D_/4);
    mma_gemm_kernel<false><<<gI, 256, SMEM_G>>>(Ah, Al, Wth+WOFF_O, Wtl+WOFF_O, bo, nullptr, attn_out, D_);

    // Normalized similarity
    norm_kernel<<<B_, 256>>>(attn_out, pt, n1_, n2_);
    score_kernel<<<dim3(B_ / 16, B_ / 16), 256>>>(n1_, n2_, score);
}

// round 5
// speedup vs baseline: 1.5878x; 1.0401x over previous
#include <cuda_runtime.h>
#include <cuda_bf16.h>
#include <math.h>
#include <stdint.h>

// Problem dims
#define B_    512
#define SQ_   49
#define SK_   50
#define DIMG_ 2048
#define DTXT_ 768
#define D_    512
#define H_    4
#define DH_   128
#define MI_   (B_*SQ_)   // 25088
#define MT_   (B_*SK_)   // 25600

// ---------------------------------------------------------------------------
// Scratch (static __device__ — no allocations allowed)
// ---------------------------------------------------------------------------
__device__ __align__(256) float g_Pimg[MI_*D_];
__device__ __align__(256) float g_Ptxt[MT_*D_];
__device__ __align__(256) float g_q[MI_*D_];
__device__ __align__(256) float g_k[MT_*D_];
__device__ __align__(256) float g_v[MT_*D_];
__device__ __align__(256) float g_a[B_*H_*SQ_*SK_];
__device__ __align__(256) float g_n1[B_*D_];
__device__ __align__(256) float g_n2[B_*D_];

// Activation bf16 hi/lo split buffers
#define AMAX_ (MI_*DIMG_)
__device__ __align__(256) __nv_bfloat16 g_Ah[AMAX_];
__device__ __align__(256) __nv_bfloat16 g_Al[AMAX_];
__device__ __align__(256) __nv_bfloat16 g_pih[MI_*D_];
__device__ __align__(256) __nv_bfloat16 g_pil[MI_*D_];
__device__ __align__(256) __nv_bfloat16 g_pth[MT_*D_];
__device__ __align__(256) __nv_bfloat16 g_ptl[MT_*D_];

// Transposed weights [N=512 rows][K cols], bf16 hi/lo, packed at offsets
#define WOFF_I1 0L
#define WOFF_T1 1048576L
#define WOFF_I2 1441792L
#define WOFF_T2 1703936L
#define WOFF_Q  1966080L
#define WOFF_K  2228224L
#define WOFF_V  2490368L
#define WOFF_O  2752512L
#define WTOT_   3014656L
__device__ __align__(256) __nv_bfloat16 g_Wth[WTOT_];
__device__ __align__(256) __nv_bfloat16 g_Wtl[WTOT_];

// ---------------------------------------------------------------------------
// Helpers
// ---------------------------------------------------------------------------
__device__ __forceinline__ uint32_t smem_u32(const void* p) {
    uint32_t a;
    asm("{ .reg .u64 t; cvta.to.shared.u64 t, %1; cvt.u32.u64 %0, t; }" : "=r"(a) : "l"(p));
    return a;
}
__device__ __forceinline__ void ldsm4(uint32_t* r, uint32_t addr) {
    asm volatile("ldmatrix.sync.aligned.m8n8.x4.shared.b16 {%0,%1,%2,%3}, [%4];"
        : "=r"(r[0]), "=r"(r[1]), "=r"(r[2]), "=r"(r[3]) : "r"(addr));
}
__device__ __forceinline__ void mma16816(float* d, const uint32_t* a, uint32_t b0, uint32_t b1) {
    asm volatile("mma.sync.aligned.m16n8k16.row.col.f32.bf16.bf16.f32 "
        "{%0,%1,%2,%3}, {%4,%5,%6,%7}, {%8,%9}, {%0,%1,%2,%3};"
        : "+f"(d[0]), "+f"(d[1]), "+f"(d[2]), "+f"(d[3])
        : "r"(a[0]), "r"(a[1]), "r"(a[2]), "r"(a[3]), "r"(b0), "r"(b1));
}
__device__ __forceinline__ void cpa16(uint32_t s, const void* g) {
    asm volatile("cp.async.ca.shared.global [%0], [%1], 16;" :: "r"(s), "l"(g));
}
#define CPA_COMMIT() asm volatile("cp.async.commit_group;" ::: "memory")
#define CPA_WAIT0()  asm volatile("cp.async.wait_group 0;" ::: "memory")

__device__ __forceinline__ void split2(float v, __nv_bfloat16& h, __nv_bfloat16& l) {
    h = __float2bfloat16_rn(v);
    l = __float2bfloat16_rn(v - __bfloat162float(h));
}
__device__ __forceinline__ uint32_t pk2(__nv_bfloat16 a, __nv_bfloat16 b) {
    unsigned short ra = *reinterpret_cast<unsigned short*>(&a);
    unsigned short rb = *reinterpret_cast<unsigned short*>(&b);
    return (uint32_t)ra | ((uint32_t)rb << 16);
}
__device__ __forceinline__ float gelu_f(float x) {
    return 0.5f * x * (1.0f + erff(x * 0.7071067811865476f));
}

// ---------------------------------------------------------------------------
// Split conversion kernels
// ---------------------------------------------------------------------------
__global__ __launch_bounds__(256) void split_kernel(const float* __restrict__ x,
    __nv_bfloat16* __restrict__ h, __nv_bfloat16* __restrict__ l, long n4)
{
    long i = (long)blockIdx.x * 256 + threadIdx.x;
    if (i >= n4) return;
    float4 v = reinterpret_cast<const float4*>(x)[i];
    __nv_bfloat16 h0,h1,h2,h3,l0,l1,l2,l3;
    split2(v.x,h0,l0); split2(v.y,h1,l1); split2(v.z,h2,l2); split2(v.w,h3,l3);
    reinterpret_cast<uint2*>(h)[i] = make_uint2(pk2(h0,h1), pk2(h2,h3));
    reinterpret_cast<uint2*>(l)[i] = make_uint2(pk2(l0,l1), pk2(l2,l3));
}

// image_features [B, DIMG, SQ] -> A[m=b*SQ+q][k] split
__global__ __launch_bounds__(256) void if_split_kernel(const float* __restrict__ IF,
    __nv_bfloat16* __restrict__ h, __nv_bfloat16* __restrict__ l) {
    __shared__ float sm[32][50];
    const int k0 = blockIdx.x * 32;
    const int b  = blockIdx.y;
    const float* base = IF + (long)b * DIMG_ * SQ_;
    for (int i = threadIdx.x; i < 32 * SQ_; i += 256) {
        int ky = i / SQ_, q = i - ky * SQ_;
        sm[ky][q] = base[(long)(k0 + ky) * SQ_ + q];
    }
    __syncthreads();
    for (int i = threadIdx.x; i < SQ_ * 32; i += 256) {
        int q = i >> 5, ky = i & 31;
        __nv_bfloat16 hb, lb; split2(sm[ky][q], hb, lb);
        long o = ((long)(b * SQ_ + q)) * DIMG_ + k0 + ky;
        h[o] = hb; l[o] = lb;
    }
}

// W [K, 512] -> Wt[n][k] bf16 hi/lo
__global__ __launch_bounds__(256) void wt_split_kernel(const float* __restrict__ W,
    __nv_bfloat16* __restrict__ th, __nv_bfloat16* __restrict__ tl, int K) {
    __shared__ float sm[32][33];
    const int k0 = blockIdx.x * 32;
    const int n0 = blockIdx.y * 32;
    for (int i = threadIdx.x; i < 1024; i += 256) {
        int r = i >> 5, c = i & 31;
        sm[r][c] = W[(long)(k0 + r) * D_ + n0 + c];
    }
    __syncthreads();
    for (int i = threadIdx.x; i < 1024; i += 256) {
        int r = i >> 5, c = i & 31;
        __nv_bfloat16 hb, lb; split2(sm[c][r], hb, lb);
        long o = (long)(n0 + r) * K + k0 + c;
        th[o] = hb; tl[o] = lb;
    }
}

// ---------------------------------------------------------------------------
// Split-bf16 tensor-core GEMM, CTA 128x128, K-chunk 32, 8 warps, 2 CTAs/SM.
// EPI: 0 = fp32 C (+res). 1 = fp32 C AND gelu-split bf16 into H/L.
// ---------------------------------------------------------------------------
#define STAGE_  40960
#define OFF_AH  0
#define OFF_AL  10240
#define OFF_BH  20480
#define OFF_BL  30720
#define SMEM_G  (2*STAGE_)

__device__ __forceinline__ void stage_cp(uint32_t sb,
    const __nv_bfloat16* __restrict__ Ah, const __nv_bfloat16* __restrict__ Al,
    const __nv_bfloat16* __restrict__ Bh, const __nv_bfloat16* __restrict__ Bl,
    int m0, int n0, int K, int kt, int tid)
{
    #pragma unroll
    for (int i = 0; i < 2; i++) {
        const int idx = tid + (i << 8);
        const int row = idx >> 2, seg = idx & 3;
        const long ga = (long)(m0 + row) * K + kt + (seg << 3);
        const long gb = (long)(n0 + row) * K + kt + (seg << 3);
        const uint32_t so = row * 80 + (seg << 4);
        cpa16(sb + OFF_AH + so, Ah + ga);
        cpa16(sb + OFF_AL + so, Al + ga);
        cpa16(sb + OFF_BH + so, Bh + gb);
        cpa16(sb + OFF_BL + so, Bl + gb);
    }
}

__device__ __forceinline__ void compute_chunk(uint32_t sb, int wid, int lane, float acc[4][4][4])
{
    const int wm = (wid & 1) << 6;
    const int wn = (wid >> 1) << 5;
    #pragma unroll
    for (int ks = 0; ks < 2; ks++) {
        uint32_t bhf[2][4], blf[2][4];
        #pragma unroll
        for (int p = 0; p < 2; p++) {
            const int row = wn + (p << 4) + (lane & 7) + (((lane >> 4) & 1) << 3);
            const int cb  = (lane >> 3) & 1;
            const uint32_t ad = sb + OFF_BH + row * 80 + (ks << 5) + (cb << 4);
            ldsm4(bhf[p], ad);
            ldsm4(blf[p], ad + (OFF_BL - OFF_BH));
        }
        #pragma unroll
        for (int mt = 0; mt < 4; mt++) {
            const int row = wm + (mt << 4) + (lane & 15);
            const int cb  = lane >> 4;
            const uint32_t ad = sb + OFF_AH + row * 80 + (ks << 5) + (cb << 4);
            uint32_t ahf[4], alf[4];
            ldsm4(ahf, ad);
            ldsm4(alf, ad + (OFF_AL - OFF_AH));
            #pragma unroll
            for (int nt2 = 0; nt2 < 4; nt2++) {
                const uint32_t b0h = bhf[nt2 >> 1][(nt2 & 1) << 1];
                const uint32_t b1h = bhf[nt2 >> 1][((nt2 & 1) << 1) + 1];
                const uint32_t b0l = blf[nt2 >> 1][(nt2 & 1) << 1];
                const uint32_t b1l = blf[nt2 >> 1][((nt2 & 1) << 1) + 1];
                mma16816(acc[mt][nt2], ahf, b0h, b1h);
                mma16816(acc[mt][nt2], ahf, b0l, b1l);
                mma16816(acc[mt][nt2], alf, b0h, b1h);
            }
        }
    }
}

template<int EPI, bool RES>
__global__ __launch_bounds__(256, 2) void mma_gemm_kernel(
    const __nv_bfloat16* __restrict__ Ah, const __nv_bfloat16* __restrict__ Al,
    const __nv_bfloat16* __restrict__ Bh_, const __nv_bfloat16* __restrict__ Bl_,
    const float* __restrict__ bias, const float* __restrict__ Res,
    float* __restrict__ C,
    __nv_bfloat16* __restrict__ Oh, __nv_bfloat16* __restrict__ Ol,
    int K)
{
    extern __shared__ __align__(16) char smem[];
    const uint32_t sbase = smem_u32(smem);
    const int tid  = threadIdx.x;
    const int wid  = tid >> 5;
    const int lane = tid & 31;
    const int m0 = blockIdx.y * 128;
    const int n0 = blockIdx.x * 128;

    float acc[4][4][4];
    #pragma unroll
    for (int i = 0; i < 4; i++)
        #pragma unroll
        for (int j = 0; j < 4; j++)
            #pragma unroll
            for (int k = 0; k < 4; k++) acc[i][j][k] = 0.f;

    const int nt = K >> 5;

    stage_cp(sbase, Ah, Al, Bh_, Bl_, m0, n0, K, 0, tid);
    CPA_COMMIT();

    for (int t = 0; t < nt; t++) {
        const int cur = t & 1;
        CPA_WAIT0();
        __syncthreads();
        if (t + 1 < nt) {
            stage_cp(sbase + (cur ^ 1) * STAGE_, Ah, Al, Bh_, Bl_, m0, n0, K, (t + 1) << 5, tid);
            CPA_COMMIT();
        }
        compute_chunk(sbase + cur * STAGE_, wid, lane, acc);
        __syncthreads();
    }

    // Epilogue
    const int wm = (wid & 1) << 6;
    const int wn = (wid >> 1) << 5;
    #pragma unroll
    for (int mt = 0; mt < 4; mt++) {
        const int r0 = m0 + wm + (mt << 4) + (lane >> 2);
        #pragma unroll
        for (int nt2 = 0; nt2 < 4; nt2++) {
            const int cc = n0 + wn + (nt2 << 3) + ((lane & 3) << 1);
            const float2 bv = *reinterpret_cast<const float2*>(bias + cc);
            float2 o0, o1;
            o0.x = acc[mt][nt2][0] + bv.x; o0.y = acc[mt][nt2][1] + bv.y;
            o1.x = acc[mt][nt2][2] + bv.x; o1.y = acc[mt][nt2][3] + bv.y;
            if (RES) {
                const float2 r0v = *reinterpret_cast<const float2*>(Res + (long)r0 * D_ + cc);
                const float2 r1v = *reinterpret_cast<const float2*>(Res + (long)(r0 + 8) * D_ + cc);
                o0.x += r0v.x; o0.y += r0v.y; o1.x += r1v.x; o1.y += r1v.y;
            }
            *reinterpret_cast<float2*>(C + (long)r0 * D_ + cc)       = o0;
            *reinterpret_cast<float2*>(C + (long)(r0 + 8) * D_ + cc) = o1;
            if (EPI == 1) {
                float g0 = gelu_f(o0.x), g1 = gelu_f(o0.y);
                float g2 = gelu_f(o1.x), g3 = gelu_f(o1.y);
                __nv_bfloat16 h0,h1,h2,h3,l0,l1,l2,l3;
                split2(g0,h0,l0); split2(g1,h1,l1); split2(g2,h2,l2); split2(g3,h3,l3);
                *reinterpret_cast<uint32_t*>(Oh + (long)r0 * D_ + cc)       = pk2(h0,h1);
                *reinterpret_cast<uint32_t*>(Ol + (long)r0 * D_ + cc)       = pk2(l0,l1);
                *reinterpret_cast<uint32_t*>(Oh + (long)(r0 + 8) * D_ + cc) = pk2(h2,h3);
                *reinterpret_cast<uint32_t*>(Ol + (long)(r0 + 8) * D_ + cc) = pk2(l2,l3);
            }
        }
    }
}

// ---------------------------------------------------------------------------
// LayerNorm in-place + fused bf16 hi/lo split
// ---------------------------------------------------------------------------
__global__ __launch_bounds__(128) void ln_split_kernel(
    float* __restrict__ X, const float* __restrict__ g, const float* __restrict__ be,
    __nv_bfloat16* __restrict__ Oh, __nv_bfloat16* __restrict__ Ol)
{
    const long row = blockIdx.x;
    float* xr = X + row * D_;
    const int t = threadIdx.x;
    float4 v = *reinterpret_cast<const float4*>(xr + t * 4);
    float s  = v.x + v.y + v.z + v.w;
    float sq = v.x*v.x + v.y*v.y + v.z*v.z + v.w*v.w;
    #pragma unroll
    for (int o = 16; o; o >>= 1) {
        s  += __shfl_xor_sync(0xffffffffu, s,  o);
        sq += __shfl_xor_sync(0xffffffffu, sq, o);
    }
    __shared__ float sh[8];
    if ((t & 31) == 0) { sh[t >> 5] = s; sh[4 + (t >> 5)] = sq; }
    __syncthreads();
    const float ts = sh[0] + sh[1] + sh[2] + sh[3];
    const float tq = sh[4] + sh[5] + sh[6] + sh[7];
    const float mu  = ts * (1.f / 512.f);
    const float var = tq * (1.f / 512.f) - mu * mu;
    const float inv = rsqrtf(var + 1e-5f);
    float4 gv = *reinterpret_cast<const float4*>(g  + t * 4);
    float4 bv = *reinterpret_cast<const float4*>(be + t * 4);
    v.x = gv.x * (v.x - mu) * inv + bv.x;
    v.y = gv.y * (v.y - mu) * inv + bv.y;
    v.z = gv.z * (v.z - mu) * inv + bv.z;
    v.w = gv.w * (v.w - mu) * inv + bv.w;
    *reinterpret_cast<float4*>(xr + t * 4) = v;
    __nv_bfloat16 h0,h1,h2,h3,l0,l1,l2,l3;
    split2(v.x,h0,l0); split2(v.y,h1,l1); split2(v.z,h2,l2); split2(v.w,h3,l3);
    reinterpret_cast<uint2*>(Oh + row * D_)[t] = make_uint2(pk2(h0,h1), pk2(h2,h3));
    reinterpret_cast<uint2*>(Ol + row * D_)[t] = make_uint2(pk2(l0,l1), pk2(l2,l3));
}

// ---------------------------------------------------------------------------
// Attention per (b,h); writes probs + pre-split bf16 output
// ---------------------------------------------------------------------------
__global__ __launch_bounds__(256) void attn_kernel(
    const float* __restrict__ q, const float* __restrict__ k,
    const float* __restrict__ v, float* __restrict__ a,
    __nv_bfloat16* __restrict__ oh, __nv_bfloat16* __restrict__ ol)
{
    const int bh = blockIdx.x;
    const int b  = bh >> 2;
    const int h  = bh & 3;
    __shared__ float kv[SK_ * DH_];
    __shared__ float s[SQ_ * SK_];
    const int tid = threadIdx.x;

    const float* kb = k + (long)b * SK_ * D_ + h * DH_;
    for (int i = tid; i < SK_ * DH_; i += 256) {
        int r = i >> 7, d = i & 127;
        kv[i] = kb[(long)r * D_ + d];
    }
    __syncthreads();

    const float* qb = q + (long)b * SQ_ * D_ + h * DH_;
    for (int i = tid; i < SQ_ * SK_; i += 256) {
        int qi = i / SK_, ki = i - qi * SK_;
        const float* qr = qb + (long)qi * D_;
        const float* kr = kv + ki * DH_;
        float accv = 0.f;
        #pragma unroll 8
        for (int d = 0; d < DH_; d++) accv += qr[d] * kr[d];
        s[i] = accv * 0.08838834764831845f;
    }
    __syncthreads();

    const float* vb = v + (long)b * SK_ * D_ + h * DH_;
    for (int i = tid; i < SK_ * DH_; i += 256) {
        int r = i >> 7, d = i & 127;
        kv[i] = vb[(long)r * D_ + d];
    }
    const int w = tid >> 5, lane = tid & 31;
    for (int row = w; row < SQ_; row += 8) {
        float mx = -1e30f;
        for (int c = lane; c < SK_; c += 32) mx = fmaxf(mx, s[row * SK_ + c]);
        #pragma unroll
        for (int off = 16; off; off >>= 1) mx = fmaxf(mx, __shfl_xor_sync(0xffffffffu, mx, off));
        float sum = 0.f;
        for (int c = lane; c < SK_; c += 32) {
            float e = __expf(s[row * SK_ + c] - mx);
            s[row * SK_ + c] = e;
            sum += e;
        }
        #pragma unroll
        for (int off = 16; off; off >>= 1) sum += __shfl_xor_sync(0xffffffffu, sum, off);
        const float inv = 1.f / sum;
        float* arow = a + ((long)(b * H_ + h) * SQ_ + row) * SK_;
        for (int c = lane; c < SK_; c += 32) {
            float p = s[row * SK_ + c] * inv;
            s[row * SK_ + c] = p;
            arow[c] = p;
        }
    }
    __syncthreads();

    for (int i = tid; i < SQ_ * DH_; i += 256) {
        int qi = i >> 7, d = i & 127;
        const float* sr = s + qi * SK_;
        float accv = 0.f;
        #pragma unroll
        for (int kk = 0; kk < SK_; kk++) accv += sr[kk] * kv[kk * DH_ + d];
        __nv_bfloat16 hb, lb; split2(accv, hb, lb);
        const long oo = ((long)b * SQ_ + qi) * D_ + h * DH_ + d;
        oh[oo] = hb; ol[oo] = lb;
    }
}

__global__ void meanh_kernel(const float* __restrict__ a, float* __restrict__ out)
{
    const int idx = blockIdx.x * 256 + threadIdx.x;
    if (idx >= B_ * SQ_ * SK_) return;
    const int b = idx / (SQ_ * SK_);
    const int r = idx - b * (SQ_ * SK_);
    float sum = 0.f;
    #pragma unroll
    for (int h = 0; h < H_; h++)
        sum += a[((long)(b * H_ + h)) * (SQ_ * SK_) + r];
    out[idx] = sum * 0.25f;
}

__global__ __launch_bounds__(256) void norm_kernel(
    const float* __restrict__ ao, const float* __restrict__ pt,
    float* __restrict__ n1, float* __restrict__ n2)
{
    const int b = blockIdx.x;
    const int t = threadIdx.x;
    float v1[2], v2[2];
    float sq1 = 0.f, sq2 = 0.f;
    #pragma unroll
    for (int j = 0; j < 2; j++) {
        const int d = t + j * 256;
        const float* base = ao + (long)b * SQ_ * D_ + d;
        float sum = 0.f;
        #pragma unroll
        for (int qq = 0; qq < SQ_; qq++) sum += base[(long)qq * D_];
        sum *= (1.f / 49.f);
        v1[j] = sum; sq1 += sum * sum;
        const float c = pt[(long)b * SK_ * D_ + d];
        v2[j] = c; sq2 += c * c;
    }
    #pragma unroll
    for (int o = 16; o; o >>= 1) {
        sq1 += __shfl_xor_sync(0xffffffffu, sq1, o);
        sq2 += __shfl_xor_sync(0xffffffffu, sq2, o);
    }
    __shared__ float s1[8], s2[8];
    if ((t & 31) == 0) { s1[t >> 5] = sq1; s2[t >> 5] = sq2; }
    __syncthreads();
    float t1 = 0.f, t2 = 0.f;
    #pragma unroll
    for (int i = 0; i < 8; i++) { t1 += s1[i]; t2 += s2[i]; }
    const float i1 = rsqrtf(t1), i2 = rsqrtf(t2);
    #pragma unroll
    for (int j = 0; j < 2; j++) {
        const int d = t + j * 256;
        n1[(long)b * D_ + d] = v1[j] * i1;
        n2[(long)b * D_ + d] = v2[j] * i2;
    }
}

__global__ __launch_bounds__(256) void score_kernel(
    const float* __restrict__ n1, const float* __restrict__ n2, float* __restrict__ out)
{
    __shared__ float As[16][17];
    __shared__ float Bs[16][17];
    const int tx = threadIdx.x & 15;
    const int ty = threadIdx.x >> 4;
    const int i0 = blockIdx.y * 16;
    const int j0 = blockIdx.x * 16;
    float acc = 0.f;
    for (int k0 = 0; k0 < D_; k0 += 16) {
        As[ty][tx] = n1[(long)(i0 + ty) * D_ + k0 + tx];
        Bs[ty][tx] = n2[(long)(j0 + ty) * D_ + k0 + tx];
        __syncthreads();
        #pragma unroll
        for (int e = 0; e < 16; e++) acc += As[ty][e] * Bs[tx][e];
        __syncthreads();
    }
    out[(long)(i0 + ty) * B_ + j0 + tx] = acc;
}

// ---------------------------------------------------------------------------
extern "C" void kernel_launch(void* const* d_in, const int* in_sizes, int n_in,
                              void* d_out, int out_size)
{
    (void)in_sizes; (void)n_in; (void)out_size;
    const float* IF  = (const float*)d_in[0];
    const float* TXT = (const float*)d_in[1];
    const float* Wi1 = (const float*)d_in[2];
    const float* bi1 = (const float*)d_in[3];
    const float* Wi2 = (const float*)d_in[4];
    const float* bi2 = (const float*)d_in[5];
    const float* gi  = (const float*)d_in[6];
    const float* bei = (const float*)d_in[7];
    const float* Wt1 = (const float*)d_in[8];
    const float* bt1 = (const float*)d_in[9];
    const float* Wt2 = (const float*)d_in[10];
    const float* bt2 = (const float*)d_in[11];
    const float* gt  = (const float*)d_in[12];
    const float* bet = (const float*)d_in[13];
    const float* Wq  = (const float*)d_in[14];
    const float* bq  = (const float*)d_in[15];
    const float* Wk  = (const float*)d_in[16];
    const float* bk  = (const float*)d_in[17];
    const float* Wv  = (const float*)d_in[18];
    const float* bv  = (const float*)d_in[19];
    const float* Wo  = (const float*)d_in[20];
    const float* bo  = (const float*)d_in[21];

    float* out       = (float*)d_out;
    float* score     = out;
    float* attn_out  = score + (long)B_ * B_;
    float* attn_w    = attn_out + (long)MI_ * D_;
    float* pi        = attn_w + (long)B_ * SQ_ * SK_;
    float* pt        = pi + (long)MI_ * D_;

    float *Pimg, *Ptxt, *qb_, *kb_, *vb_, *ab_, *n1_, *n2_;
    __nv_bfloat16 *Ah, *Al, *pih, *pil, *pth, *ptl, *Wth, *Wtl;
    cudaGetSymbolAddress((void**)&Pimg, g_Pimg);
    cudaGetSymbolAddress((void**)&Ptxt, g_Ptxt);
    cudaGetSymbolAddress((void**)&qb_,  g_q);
    cudaGetSymbolAddress((void**)&kb_,  g_k);
    cudaGetSymbolAddress((void**)&vb_,  g_v);
    cudaGetSymbolAddress((void**)&ab_,  g_a);
    cudaGetSymbolAddress((void**)&n1_,  g_n1);
    cudaGetSymbolAddress((void**)&n2_,  g_n2);
    cudaGetSymbolAddress((void**)&Ah,   g_Ah);
    cudaGetSymbolAddress((void**)&Al,   g_Al);
    cudaGetSymbolAddress((void**)&pih,  g_pih);
    cudaGetSymbolAddress((void**)&pil,  g_pil);
    cudaGetSymbolAddress((void**)&pth,  g_pth);
    cudaGetSymbolAddress((void**)&ptl,  g_ptl);
    cudaGetSymbolAddress((void**)&Wth,  g_Wth);
    cudaGetSymbolAddress((void**)&Wtl,  g_Wtl);

    cudaFuncSetAttribute(mma_gemm_kernel<0,false>, cudaFuncAttributeMaxDynamicSharedMemorySize, SMEM_G);
    cudaFuncSetAttribute(mma_gemm_kernel<0,true>,  cudaFuncAttributeMaxDynamicSharedMemorySize, SMEM_G);
    cudaFuncSetAttribute(mma_gemm_kernel<1,false>, cudaFuncAttributeMaxDynamicSharedMemorySize, SMEM_G);

    const dim3 gI(4, MI_ / 128);   // (4, 196)
    const dim3 gT(4, MT_ / 128);   // (4, 200)

    // Weight transpose+split (bf16 hi/lo)
    wt_split_kernel<<<dim3(DIMG_/32, 16), 256>>>(Wi1, Wth + WOFF_I1, Wtl + WOFF_I1, DIMG_);
    wt_split_kernel<<<dim3(DTXT_/32, 16), 256>>>(Wt1, Wth + WOFF_T1, Wtl + WOFF_T1, DTXT_);
    wt_split_kernel<<<dim3(D_/32, 16), 256>>>(Wi2, Wth + WOFF_I2, Wtl + WOFF_I2, D_);
    wt_split_kernel<<<dim3(D_/32, 16), 256>>>(Wt2, Wth + WOFF_T2, Wtl + WOFF_T2, D_);
    wt_split_kernel<<<dim3(D_/32, 16), 256>>>(Wq,  Wth + WOFF_Q,  Wtl + WOFF_Q,  D_);
    wt_split_kernel<<<dim3(D_/32, 16), 256>>>(Wk,  Wth + WOFF_K,  Wtl + WOFF_K,  D_);
    wt_split_kernel<<<dim3(D_/32, 16), 256>>>(Wv,  Wth + WOFF_V,  Wtl + WOFF_V,  D_);
    wt_split_kernel<<<dim3(D_/32, 16), 256>>>(Wo,  Wth + WOFF_O,  Wtl + WOFF_O,  D_);

    // Image head: GEMM1 writes Pimg fp32 + gelu-split into pih/pil
    if_split_kernel<<<dim3(DIMG_/32, B_), 256>>>(IF, Ah, Al);
    mma_gemm_kernel<1,false><<<gI, 256, SMEM_G>>>(Ah, Al, Wth+WOFF_I1, Wtl+WOFF_I1, bi1, nullptr, Pimg, pih, pil, DIMG_);
    mma_gemm_kernel<0,true ><<<gI, 256, SMEM_G>>>(pih, pil, Wth+WOFF_I2, Wtl+WOFF_I2, bi2, Pimg, pi, nullptr, nullptr, D_);
    ln_split_kernel<<<MI_, 128>>>(pi, gi, bei, pih, pil);

    // Text head
    split_kernel<<<((long)MT_*DTXT_/4 + 255)/256, 256>>>(TXT, Ah, Al, (long)MT_*DTXT_/4);
    mma_gemm_kernel<1,false><<<gT, 256, SMEM_G>>>(Ah, Al, Wth+WOFF_T1, Wtl+WOFF_T1, bt1, nullptr, Ptxt, pth, ptl, DTXT_);
    mma_gemm_kernel<0,true ><<<gT, 256, SMEM_G>>>(pth, ptl, Wth+WOFF_T2, Wtl+WOFF_T2, bt2, Ptxt, pt, nullptr, nullptr, D_);
    ln_split_kernel<<<MT_, 128>>>(pt, gt, bet, pth, ptl);

    // QKV (pih/pil = split(pi), pth/ptl = split(pt))
    mma_gemm_kernel<0,false><<<gI, 256, SMEM_G>>>(pih, pil, Wth+WOFF_Q, Wtl+WOFF_Q, bq, nullptr, qb_, nullptr, nullptr, D_);
    mma_gemm_kernel<0,false><<<gT, 256, SMEM_G>>>(pth, ptl, Wth+WOFF_K, Wtl+WOFF_K, bk, nullptr, kb_, nullptr, nullptr, D_);
    mma_gemm_kernel<0,false><<<gT, 256, SMEM_G>>>(pth, ptl, Wth+WOFF_V, Wtl+WOFF_V, bv, nullptr, vb_, nullptr, nullptr, D_);

    // Attention (writes probs + pre-split o into Ah/Al)
    attn_kernel<<<B_ * H_, 256>>>(qb_, kb_, vb_, ab_, Ah, Al);
    meanh_kernel<<<(B_ * SQ_ * SK_ + 255) / 256, 256>>>(ab_, attn_w);

    // Output projection
    mma_gemm_kernel<0,false><<<gI, 256, SMEM_G>>>(Ah, Al, Wth+WOFF_O, Wtl+WOFF_O, bo, nullptr, attn_out, nullptr, nullptr, D_);

    // Normalized similarity
    norm_kernel<<<B_, 256>>>(attn_out, pt, n1_, n2_);
    score_kernel<<<dim3(B_ / 16, B_ / 16), 256>>>(n1_, n2_, score);
}

// round 6
// speedup vs baseline: 1.8238x; 1.1486x over previous
#include <cuda_runtime.h>
#include <cuda_fp16.h>
#include <math.h>
#include <stdint.h>

// Problem dims
#define B_    512
#define SQ_   49
#define SK_   50
#define DIMG_ 2048
#define DTXT_ 768
#define D_    512
#define H_    4
#define DH_   128
#define MI_   (B_*SQ_)   // 25088
#define MT_   (B_*SK_)   // 25600

// ---------------------------------------------------------------------------
// Scratch (static __device__ — no allocations allowed)
// ---------------------------------------------------------------------------
__device__ __align__(256) float g_Pimg[MI_*D_];
__device__ __align__(256) float g_Ptxt[MT_*D_];
__device__ __align__(256) float g_q[MI_*D_];
__device__ __align__(256) float g_k[MT_*D_];
__device__ __align__(256) float g_v[MT_*D_];
__device__ __align__(256) float g_a[B_*H_*SQ_*SK_];
__device__ __align__(256) float g_n1[B_*D_];
__device__ __align__(256) float g_n2[B_*D_];

// fp16 activation buffers
#define AMAX_ (MI_*DIMG_)
__device__ __align__(256) __half g_Af[AMAX_];
__device__ __align__(256) __half g_pif[MI_*D_];
__device__ __align__(256) __half g_ptf[MT_*D_];

// Transposed weights [N=512 rows][K cols], fp16 hi/lo, packed at offsets
#define WOFF_I1 0L
#define WOFF_T1 1048576L
#define WOFF_I2 1441792L
#define WOFF_T2 1703936L
#define WOFF_Q  1966080L
#define WOFF_K  2228224L
#define WOFF_V  2490368L
#define WOFF_O  2752512L
#define WTOT_   3014656L
__device__ __align__(256) __half g_Wh[WTOT_];
__device__ __align__(256) __half g_Wl[WTOT_];

// ---------------------------------------------------------------------------
// Helpers
// ---------------------------------------------------------------------------
__device__ __forceinline__ uint32_t smem_u32(const void* p) {
    uint32_t a;
    asm("{ .reg .u64 t; cvta.to.shared.u64 t, %1; cvt.u32.u64 %0, t; }" : "=r"(a) : "l"(p));
    return a;
}
__device__ __forceinline__ void ldsm4(uint32_t* r, uint32_t addr) {
    asm volatile("ldmatrix.sync.aligned.m8n8.x4.shared.b16 {%0,%1,%2,%3}, [%4];"
        : "=r"(r[0]), "=r"(r[1]), "=r"(r[2]), "=r"(r[3]) : "r"(addr));
}
__device__ __forceinline__ void mma16816(float* d, const uint32_t* a, uint32_t b0, uint32_t b1) {
    asm volatile("mma.sync.aligned.m16n8k16.row.col.f32.f16.f16.f32 "
        "{%0,%1,%2,%3}, {%4,%5,%6,%7}, {%8,%9}, {%0,%1,%2,%3};"
        : "+f"(d[0]), "+f"(d[1]), "+f"(d[2]), "+f"(d[3])
        : "r"(a[0]), "r"(a[1]), "r"(a[2]), "r"(a[3]), "r"(b0), "r"(b1));
}
__device__ __forceinline__ void cpa16(uint32_t s, const void* g) {
    asm volatile("cp.async.ca.shared.global [%0], [%1], 16;" :: "r"(s), "l"(g));
}
#define CPA_COMMIT() asm volatile("cp.async.commit_group;" ::: "memory")
#define CPA_WAIT0()  asm volatile("cp.async.wait_group 0;" ::: "memory")

__device__ __forceinline__ void wsplit(float v, __half& h, __half& l) {
    h = __float2half_rn(v);
    l = __float2half_rn(v - __half2float(h));
}
__device__ __forceinline__ uint32_t pkh(__half a, __half b) {
    unsigned short ra = *reinterpret_cast<unsigned short*>(&a);
    unsigned short rb = *reinterpret_cast<unsigned short*>(&b);
    return (uint32_t)ra | ((uint32_t)rb << 16);
}
__device__ __forceinline__ float gelu_f(float x) {
    return 0.5f * x * (1.0f + erff(x * 0.7071067811865476f));
}

// ---------------------------------------------------------------------------
// Conversion kernels
// ---------------------------------------------------------------------------
// fp32 -> fp16, 4 elems/thread
__global__ __launch_bounds__(256) void cvt_kernel(const float* __restrict__ x,
    __half* __restrict__ f, long n4)
{
    long i = (long)blockIdx.x * 256 + threadIdx.x;
    if (i >= n4) return;
    float4 v = reinterpret_cast<const float4*>(x)[i];
    reinterpret_cast<uint2*>(f)[i] = make_uint2(
        pkh(__float2half_rn(v.x), __float2half_rn(v.y)),
        pkh(__float2half_rn(v.z), __float2half_rn(v.w)));
}

// image_features [B, DIMG, SQ] -> A[m=b*SQ+q][k] fp16
__global__ __launch_bounds__(256) void if_cvt_kernel(const float* __restrict__ IF,
    __half* __restrict__ f) {
    __shared__ float sm[32][50];
    const int k0 = blockIdx.x * 32;
    const int b  = blockIdx.y;
    const float* base = IF + (long)b * DIMG_ * SQ_;
    for (int i = threadIdx.x; i < 32 * SQ_; i += 256) {
        int ky = i / SQ_, q = i - ky * SQ_;
        sm[ky][q] = base[(long)(k0 + ky) * SQ_ + q];
    }
    __syncthreads();
    for (int i = threadIdx.x; i < SQ_ * 32; i += 256) {
        int q = i >> 5, ky = i & 31;
        f[((long)(b * SQ_ + q)) * DIMG_ + k0 + ky] = __float2half_rn(sm[ky][q]);
    }
}

// W [K, 512] -> Wt[n][k] fp16 hi/lo
__global__ __launch_bounds__(256) void wt_split_kernel(const float* __restrict__ W,
    __half* __restrict__ th, __half* __restrict__ tl, int K) {
    __shared__ float sm[32][33];
    const int k0 = blockIdx.x * 32;
    const int n0 = blockIdx.y * 32;
    for (int i = threadIdx.x; i < 1024; i += 256) {
        int r = i >> 5, c = i & 31;
        sm[r][c] = W[(long)(k0 + r) * D_ + n0 + c];
    }
    __syncthreads();
    for (int i = threadIdx.x; i < 1024; i += 256) {
        int r = i >> 5, c = i & 31;
        __half hb, lb; wsplit(sm[c][r], hb, lb);
        long o = (long)(n0 + r) * K + k0 + c;
        th[o] = hb; tl[o] = lb;
    }
}

// ---------------------------------------------------------------------------
// 2-term fp16 tensor-core GEMM: C = A(fp16) @ (Wh + Wl) + bias (+Res)
// CTA 128x128, K-chunk 32, 8 warps (warp tile 64x32), cp.async double buffer.
// EPI: 0 = fp32 C. 1 = fp32 C AND gelu->fp16 into Of.
// ---------------------------------------------------------------------------
#define STAGE_  30720
#define OFF_A   0
#define OFF_BH  10240
#define OFF_BL  20480
#define SMEM_G  (2*STAGE_)

__device__ __forceinline__ void stage_cp(uint32_t sb,
    const __half* __restrict__ Af, const __half* __restrict__ Bh,
    const __half* __restrict__ Bl,
    int m0, int n0, int K, int kt, int tid)
{
    #pragma unroll
    for (int i = 0; i < 2; i++) {
        const int idx = tid + (i << 8);
        const int row = idx >> 2, seg = idx & 3;
        const long ga = (long)(m0 + row) * K + kt + (seg << 3);
        const long gb = (long)(n0 + row) * K + kt + (seg << 3);
        const uint32_t so = row * 80 + (seg << 4);
        cpa16(sb + OFF_A  + so, Af + ga);
        cpa16(sb + OFF_BH + so, Bh + gb);
        cpa16(sb + OFF_BL + so, Bl + gb);
    }
}

__device__ __forceinline__ void compute_chunk(uint32_t sb, int wid, int lane, float acc[4][4][4])
{
    const int wm = (wid & 1) << 6;
    const int wn = (wid >> 1) << 5;
    #pragma unroll
    for (int ks = 0; ks < 2; ks++) {
        uint32_t bhf[2][4], blf[2][4];
        #pragma unroll
        for (int p = 0; p < 2; p++) {
            const int row = wn + (p << 4) + (lane & 7) + (((lane >> 4) & 1) << 3);
            const int cb  = (lane >> 3) & 1;
            const uint32_t ad = sb + OFF_BH + row * 80 + (ks << 5) + (cb << 4);
            ldsm4(bhf[p], ad);
            ldsm4(blf[p], ad + (OFF_BL - OFF_BH));
        }
        #pragma unroll
        for (int mt = 0; mt < 4; mt++) {
            const int row = wm + (mt << 4) + (lane & 15);
            const int cb  = lane >> 4;
            uint32_t ahf[4];
            ldsm4(ahf, sb + OFF_A + row * 80 + (ks << 5) + (cb << 4));
            #pragma unroll
            for (int nt2 = 0; nt2 < 4; nt2++) {
                const uint32_t b0h = bhf[nt2 >> 1][(nt2 & 1) << 1];
                const uint32_t b1h = bhf[nt2 >> 1][((nt2 & 1) << 1) + 1];
                const uint32_t b0l = blf[nt2 >> 1][(nt2 & 1) << 1];
                const uint32_t b1l = blf[nt2 >> 1][((nt2 & 1) << 1) + 1];
                mma16816(acc[mt][nt2], ahf, b0h, b1h);
                mma16816(acc[mt][nt2], ahf, b0l, b1l);
            }
        }
    }
}

template<int EPI, bool RES>
__global__ __launch_bounds__(256, 2) void mma_gemm_kernel(
    const __half* __restrict__ Af,
    const __half* __restrict__ Bh_, const __half* __restrict__ Bl_,
    const float* __restrict__ bias, const float* __restrict__ Res,
    float* __restrict__ C, __half* __restrict__ Of, int K)
{
    extern __shared__ __align__(16) char smem[];
    const uint32_t sbase = smem_u32(smem);
    const int tid  = threadIdx.x;
    const int wid  = tid >> 5;
    const int lane = tid & 31;
    const int m0 = blockIdx.y * 128;
    const int n0 = blockIdx.x * 128;

    float acc[4][4][4];
    #pragma unroll
    for (int i = 0; i < 4; i++)
        #pragma unroll
        for (int j = 0; j < 4; j++)
            #pragma unroll
            for (int k = 0; k < 4; k++) acc[i][j][k] = 0.f;

    const int nt = K >> 5;

    stage_cp(sbase, Af, Bh_, Bl_, m0, n0, K, 0, tid);
    CPA_COMMIT();

    for (int t = 0; t < nt; t++) {
        const int cur = t & 1;
        CPA_WAIT0();
        __syncthreads();
        if (t + 1 < nt) {
            stage_cp(sbase + (cur ^ 1) * STAGE_, Af, Bh_, Bl_, m0, n0, K, (t + 1) << 5, tid);
            CPA_COMMIT();
        }
        compute_chunk(sbase + cur * STAGE_, wid, lane, acc);
        __syncthreads();
    }

    // Epilogue
    const int wm = (wid & 1) << 6;
    const int wn = (wid >> 1) << 5;
    #pragma unroll
    for (int mt = 0; mt < 4; mt++) {
        const int r0 = m0 + wm + (mt << 4) + (lane >> 2);
        #pragma unroll
        for (int nt2 = 0; nt2 < 4; nt2++) {
            const int cc = n0 + wn + (nt2 << 3) + ((lane & 3) << 1);
            const float2 bv = *reinterpret_cast<const float2*>(bias + cc);
            float2 o0, o1;
            o0.x = acc[mt][nt2][0] + bv.x; o0.y = acc[mt][nt2][1] + bv.y;
            o1.x = acc[mt][nt2][2] + bv.x; o1.y = acc[mt][nt2][3] + bv.y;
            if (RES) {
                const float2 r0v = *reinterpret_cast<const float2*>(Res + (long)r0 * D_ + cc);
                const float2 r1v = *reinterpret_cast<const float2*>(Res + (long)(r0 + 8) * D_ + cc);
                o0.x += r0v.x; o0.y += r0v.y; o1.x += r1v.x; o1.y += r1v.y;
            }
            *reinterpret_cast<float2*>(C + (long)r0 * D_ + cc)       = o0;
            *reinterpret_cast<float2*>(C + (long)(r0 + 8) * D_ + cc) = o1;
            if (EPI == 1) {
                *reinterpret_cast<uint32_t*>(Of + (long)r0 * D_ + cc) =
                    pkh(__float2half_rn(gelu_f(o0.x)), __float2half_rn(gelu_f(o0.y)));
                *reinterpret_cast<uint32_t*>(Of + (long)(r0 + 8) * D_ + cc) =
                    pkh(__float2half_rn(gelu_f(o1.x)), __float2half_rn(gelu_f(o1.y)));
            }
        }
    }
}

// ---------------------------------------------------------------------------
// LayerNorm in-place + fused fp16 convert
// ---------------------------------------------------------------------------
__global__ __launch_bounds__(128) void ln_cvt_kernel(
    float* __restrict__ X, const float* __restrict__ g, const float* __restrict__ be,
    __half* __restrict__ Of)
{
    const long row = blockIdx.x;
    float* xr = X + row * D_;
    const int t = threadIdx.x;
    float4 v = *reinterpret_cast<const float4*>(xr + t * 4);
    float s  = v.x + v.y + v.z + v.w;
    float sq = v.x*v.x + v.y*v.y + v.z*v.z + v.w*v.w;
    #pragma unroll
    for (int o = 16; o; o >>= 1) {
        s  += __shfl_xor_sync(0xffffffffu, s,  o);
        sq += __shfl_xor_sync(0xffffffffu, sq, o);
    }
    __shared__ float sh[8];
    if ((t & 31) == 0) { sh[t >> 5] = s; sh[4 + (t >> 5)] = sq; }
    __syncthreads();
    const float ts = sh[0] + sh[1] + sh[2] + sh[3];
    const float tq = sh[4] + sh[5] + sh[6] + sh[7];
    const float mu  = ts * (1.f / 512.f);
    const float var = tq * (1.f / 512.f) - mu * mu;
    const float inv = rsqrtf(var + 1e-5f);
    float4 gv = *reinterpret_cast<const float4*>(g  + t * 4);
    float4 bv = *reinterpret_cast<const float4*>(be + t * 4);
    v.x = gv.x * (v.x - mu) * inv + bv.x;
    v.y = gv.y * (v.y - mu) * inv + bv.y;
    v.z = gv.z * (v.z - mu) * inv + bv.z;
    v.w = gv.w * (v.w - mu) * inv + bv.w;
    *reinterpret_cast<float4*>(xr + t * 4) = v;
    reinterpret_cast<uint2*>(Of + row * D_)[t] = make_uint2(
        pkh(__float2half_rn(v.x), __float2half_rn(v.y)),
        pkh(__float2half_rn(v.z), __float2half_rn(v.w)));
}

// ---------------------------------------------------------------------------
// Attention per (b,h); writes probs + fp16 output
// ---------------------------------------------------------------------------
__global__ __launch_bounds__(256) void attn_kernel(
    const float* __restrict__ q, const float* __restrict__ k,
    const float* __restrict__ v, float* __restrict__ a,
    __half* __restrict__ of)
{
    const int bh = blockIdx.x;
    const int b  = bh >> 2;
    const int h  = bh & 3;
    __shared__ float kv[SK_ * DH_];
    __shared__ float s[SQ_ * SK_];
    const int tid = threadIdx.x;

    const float* kb = k + (long)b * SK_ * D_ + h * DH_;
    for (int i = tid; i < SK_ * DH_; i += 256) {
        int r = i >> 7, d = i & 127;
        kv[i] = kb[(long)r * D_ + d];
    }
    __syncthreads();

    const float* qb = q + (long)b * SQ_ * D_ + h * DH_;
    for (int i = tid; i < SQ_ * SK_; i += 256) {
        int qi = i / SK_, ki = i - qi * SK_;
        const float* qr = qb + (long)qi * D_;
        const float* kr = kv + ki * DH_;
        float accv = 0.f;
        #pragma unroll 8
        for (int d = 0; d < DH_; d++) accv += qr[d] * kr[d];
        s[i] = accv * 0.08838834764831845f;
    }
    __syncthreads();

    const float* vb = v + (long)b * SK_ * D_ + h * DH_;
    for (int i = tid; i < SK_ * DH_; i += 256) {
        int r = i >> 7, d = i & 127;
        kv[i] = vb[(long)r * D_ + d];
    }
    const int w = tid >> 5, lane = tid & 31;
    for (int row = w; row < SQ_; row += 8) {
        float mx = -1e30f;
        for (int c = lane; c < SK_; c += 32) mx = fmaxf(mx, s[row * SK_ + c]);
        #pragma unroll
        for (int off = 16; off; off >>= 1) mx = fmaxf(mx, __shfl_xor_sync(0xffffffffu, mx, off));
        float sum = 0.f;
        for (int c = lane; c < SK_; c += 32) {
            float e = __expf(s[row * SK_ + c] - mx);
            s[row * SK_ + c] = e;
            sum += e;
        }
        #pragma unroll
        for (int off = 16; off; off >>= 1) sum += __shfl_xor_sync(0xffffffffu, sum, off);
        const float inv = 1.f / sum;
        float* arow = a + ((long)(b * H_ + h) * SQ_ + row) * SK_;
        for (int c = lane; c < SK_; c += 32) {
            float p = s[row * SK_ + c] * inv;
            s[row * SK_ + c] = p;
            arow[c] = p;
        }
    }
    __syncthreads();

    for (int i = tid; i < SQ_ * DH_; i += 256) {
        int qi = i >> 7, d = i & 127;
        const float* sr = s + qi * SK_;
        float accv = 0.f;
        #pragma unroll
        for (int kk = 0; kk < SK_; kk++) accv += sr[kk] * kv[kk * DH_ + d];
        of[((long)b * SQ_ + qi) * D_ + h * DH_ + d] = __float2half_rn(accv);
    }
}

__global__ void meanh_kernel(const float* __restrict__ a, float* __restrict__ out)
{
    const int idx = blockIdx.x * 256 + threadIdx.x;
    if (idx >= B_ * SQ_ * SK_) return;
    const int b = idx / (SQ_ * SK_);
    const int r = idx - b * (SQ_ * SK_);
    float sum = 0.f;
    #pragma unroll
    for (int h = 0; h < H_; h++)
        sum += a[((long)(b * H_ + h)) * (SQ_ * SK_) + r];
    out[idx] = sum * 0.25f;
}

__global__ __launch_bounds__(256) void norm_kernel(
    const float* __restrict__ ao, const float* __restrict__ pt,
    float* __restrict__ n1, float* __restrict__ n2)
{
    const int b = blockIdx.x;
    const int t = threadIdx.x;
    float v1[2], v2[2];
    float sq1 = 0.f, sq2 = 0.f;
    #pragma unroll
    for (int j = 0; j < 2; j++) {
        const int d = t + j * 256;
        const float* base = ao + (long)b * SQ_ * D_ + d;
        float sum = 0.f;
        #pragma unroll
        for (int qq = 0; qq < SQ_; qq++) sum += base[(long)qq * D_];
        sum *= (1.f / 49.f);
        v1[j] = sum; sq1 += sum * sum;
        const float c = pt[(long)b * SK_ * D_ + d];
        v2[j] = c; sq2 += c * c;
    }
    #pragma unroll
    for (int o = 16; o; o >>= 1) {
        sq1 += __shfl_xor_sync(0xffffffffu, sq1, o);
        sq2 += __shfl_xor_sync(0xffffffffu, sq2, o);
    }
    __shared__ float s1[8], s2[8];
    if ((t & 31) == 0) { s1[t >> 5] = sq1; s2[t >> 5] = sq2; }
    __syncthreads();
    float t1 = 0.f, t2 = 0.f;
    #pragma unroll
    for (int i = 0; i < 8; i++) { t1 += s1[i]; t2 += s2[i]; }
    const float i1 = rsqrtf(t1), i2 = rsqrtf(t2);
    #pragma unroll
    for (int j = 0; j < 2; j++) {
        const int d = t + j * 256;
        n1[(long)b * D_ + d] = v1[j] * i1;
        n2[(long)b * D_ + d] = v2[j] * i2;
    }
}

__global__ __launch_bounds__(256) void score_kernel(
    const float* __restrict__ n1, const float* __restrict__ n2, float* __restrict__ out)
{
    __shared__ float As[16][17];
    __shared__ float Bs[16][17];
    const int tx = threadIdx.x & 15;
    const int ty = threadIdx.x >> 4;
    const int i0 = blockIdx.y * 16;
    const int j0 = blockIdx.x * 16;
    float acc = 0.f;
    for (int k0 = 0; k0 < D_; k0 += 16) {
        As[ty][tx] = n1[(long)(i0 + ty) * D_ + k0 + tx];
        Bs[ty][tx] = n2[(long)(j0 + ty) * D_ + k0 + tx];
        __syncthreads();
        #pragma unroll
        for (int e = 0; e < 16; e++) acc += As[ty][e] * Bs[tx][e];
        __syncthreads();
    }
    out[(long)(i0 + ty) * B_ + j0 + tx] = acc;
}

// ---------------------------------------------------------------------------
extern "C" void kernel_launch(void* const* d_in, const int* in_sizes, int n_in,
                              void* d_out, int out_size)
{
    (void)in_sizes; (void)n_in; (void)out_size;
    const float* IF  = (const float*)d_in[0];
    const float* TXT = (const float*)d_in[1];
    const float* Wi1 = (const float*)d_in[2];
    const float* bi1 = (const float*)d_in[3];
    const float* Wi2 = (const float*)d_in[4];
    const float* bi2 = (const float*)d_in[5];
    const float* gi  = (const float*)d_in[6];
    const float* bei = (const float*)d_in[7];
    const float* Wt1 = (const float*)d_in[8];
    const float* bt1 = (const float*)d_in[9];
    const float* Wt2 = (const float*)d_in[10];
    const float* bt2 = (const float*)d_in[11];
    const float* gt  = (const float*)d_in[12];
    const float* bet = (const float*)d_in[13];
    const float* Wq  = (const float*)d_in[14];
    const float* bq  = (const float*)d_in[15];
    const float* Wk  = (const float*)d_in[16];
    const float* bk  = (const float*)d_in[17];
    const float* Wv  = (const float*)d_in[18];
    const float* bv  = (const float*)d_in[19];
    const float* Wo  = (const float*)d_in[20];
    const float* bo  = (const float*)d_in[21];

    float* out       = (float*)d_out;
    float* score     = out;
    float* attn_out  = score + (long)B_ * B_;
    float* attn_w    = attn_out + (long)MI_ * D_;
    float* pi        = attn_w + (long)B_ * SQ_ * SK_;
    float* pt        = pi + (long)MI_ * D_;

    float *Pimg, *Ptxt, *qb_, *kb_, *vb_, *ab_, *n1_, *n2_;
    __half *Af, *pif, *ptf, *Wh, *Wl;
    cudaGetSymbolAddress((void**)&Pimg, g_Pimg);
    cudaGetSymbolAddress((void**)&Ptxt, g_Ptxt);
    cudaGetSymbolAddress((void**)&qb_,  g_q);
    cudaGetSymbolAddress((void**)&kb_,  g_k);
    cudaGetSymbolAddress((void**)&vb_,  g_v);
    cudaGetSymbolAddress((void**)&ab_,  g_a);
    cudaGetSymbolAddress((void**)&n1_,  g_n1);
    cudaGetSymbolAddress((void**)&n2_,  g_n2);
    cudaGetSymbolAddress((void**)&Af,   g_Af);
    cudaGetSymbolAddress((void**)&pif,  g_pif);
    cudaGetSymbolAddress((void**)&ptf,  g_ptf);
    cudaGetSymbolAddress((void**)&Wh,   g_Wh);
    cudaGetSymbolAddress((void**)&Wl,   g_Wl);

    cudaFuncSetAttribute(mma_gemm_kernel<0,false>, cudaFuncAttributeMaxDynamicSharedMemorySize, SMEM_G);
    cudaFuncSetAttribute(mma_gemm_kernel<0,true>,  cudaFuncAttributeMaxDynamicSharedMemorySize, SMEM_G);
    cudaFuncSetAttribute(mma_gemm_kernel<1,false>, cudaFuncAttributeMaxDynamicSharedMemorySize, SMEM_G);

    const dim3 gI(4, MI_ / 128);   // (4, 196)
    const dim3 gT(4, MT_ / 128);   // (4, 200)

    // Launches 0-4: ncu (-s 5) skips these; launch 5 is the big image GEMM.
    wt_split_kernel<<<dim3(DIMG_/32, 16), 256>>>(Wi1, Wh + WOFF_I1, Wl + WOFF_I1, DIMG_); // 0
    if_cvt_kernel<<<dim3(DIMG_/32, B_), 256>>>(IF, Af);                                   // 1
    wt_split_kernel<<<dim3(DTXT_/32, 16), 256>>>(Wt1, Wh + WOFF_T1, Wl + WOFF_T1, DTXT_); // 2
    wt_split_kernel<<<dim3(D_/32, 16), 256>>>(Wi2, Wh + WOFF_I2, Wl + WOFF_I2, D_);       // 3
    wt_split_kernel<<<dim3(D_/32, 16), 256>>>(Wt2, Wh + WOFF_T2, Wl + WOFF_T2, D_);       // 4

    // 5: image GEMM1 (K=2048) — ncu capture target
    mma_gemm_kernel<1,false><<<gI, 256, SMEM_G>>>(Af, Wh+WOFF_I1, Wl+WOFF_I1, bi1, nullptr, Pimg, pif, DIMG_);
    mma_gemm_kernel<0,true ><<<gI, 256, SMEM_G>>>(pif, Wh+WOFF_I2, Wl+WOFF_I2, bi2, Pimg, pi, nullptr, D_);
    ln_cvt_kernel<<<MI_, 128>>>(pi, gi, bei, pif);

    // Text head
    cvt_kernel<<<((long)MT_*DTXT_/4 + 255)/256, 256>>>(TXT, Af, (long)MT_*DTXT_/4);
    mma_gemm_kernel<1,false><<<gT, 256, SMEM_G>>>(Af, Wh+WOFF_T1, Wl+WOFF_T1, bt1, nullptr, Ptxt, ptf, DTXT_);
    mma_gemm_kernel<0,true ><<<gT, 256, SMEM_G>>>(ptf, Wh+WOFF_T2, Wl+WOFF_T2, bt2, Ptxt, pt, nullptr, D_);
    ln_cvt_kernel<<<MT_, 128>>>(pt, gt, bet, ptf);

    // Remaining weight splits
    wt_split_kernel<<<dim3(D_/32, 16), 256>>>(Wq, Wh + WOFF_Q, Wl + WOFF_Q, D_);
    wt_split_kernel<<<dim3(D_/32, 16), 256>>>(Wk, Wh + WOFF_K, Wl + WOFF_K, D_);
    wt_split_kernel<<<dim3(D_/32, 16), 256>>>(Wv, Wh + WOFF_V, Wl + WOFF_V, D_);
    wt_split_kernel<<<dim3(D_/32, 16), 256>>>(Wo, Wh + WOFF_O, Wl + WOFF_O, D_);

    // QKV
    mma_gemm_kernel<0,false><<<gI, 256, SMEM_G>>>(pif, Wh+WOFF_Q, Wl+WOFF_Q, bq, nullptr, qb_, nullptr, D_);
    mma_gemm_kernel<0,false><<<gT, 256, SMEM_G>>>(ptf, Wh+WOFF_K, Wl+WOFF_K, bk, nullptr, kb_, nullptr, D_);
    mma_gemm_kernel<0,false><<<gT, 256, SMEM_G>>>(ptf, Wh+WOFF_V, Wl+WOFF_V, bv, nullptr, vb_, nullptr, D_);

    // Attention (writes probs + fp16 o into Af)
    attn_kernel<<<B_ * H_, 256>>>(qb_, kb_, vb_, ab_, Af);
    meanh_kernel<<<(B_ * SQ_ * SK_ + 255) / 256, 256>>>(ab_, attn_w);

    // Output projection
    mma_gemm_kernel<0,false><<<gI, 256, SMEM_G>>>(Af, Wh+WOFF_O, Wl+WOFF_O, bo, nullptr, attn_out, nullptr, D_);

    // Normalized similarity
    norm_kernel<<<B_, 256>>>(attn_out, pt, n1_, n2_);
    score_kernel<<<dim3(B_ / 16, B_ / 16), 256>>>(n1_, n2_, score);
}

// round 10
// speedup vs baseline: 2.0465x; 1.1221x over previous
#include <cuda_runtime.h>
#include <cuda_fp16.h>
#include <math.h>
#include <stdint.h>

// Problem dims
#define B_    512
#define SQ_   49
#define SK_   50
#define DIMG_ 2048
#define DTXT_ 768
#define D_    512
#define H_    4
#define DH_   128
#define MI_   (B_*SQ_)   // 25088
#define MT_   (B_*SK_)   // 25600

// ---------------------------------------------------------------------------
// Scratch (static __device__ — no allocations allowed)
// ---------------------------------------------------------------------------
__device__ __align__(256) float g_Pimg[MI_*D_];
__device__ __align__(256) float g_Ptxt[MT_*D_];
__device__ __align__(256) float g_q[MI_*D_];
__device__ __align__(256) float g_k[MT_*D_];
__device__ __align__(256) float g_v[MT_*D_];
__device__ __align__(256) float g_a[B_*H_*SQ_*SK_];
__device__ __align__(256) float g_n1[B_*D_];
__device__ __align__(256) float g_n2[B_*D_];

// fp16 activation buffers
#define AMAX_ (MI_*DIMG_)
__device__ __align__(256) __half g_Af[AMAX_];
__device__ __align__(256) __half g_pif[MI_*D_];
__device__ __align__(256) __half g_ptf[MT_*D_];

// Transposed weights [N=512 rows][K cols], fp16, packed at offsets
#define WOFF_I1 0L
#define WOFF_T1 1048576L
#define WOFF_I2 1441792L
#define WOFF_T2 1703936L
#define WOFF_Q  1966080L
#define WOFF_K  2228224L
#define WOFF_V  2490368L
#define WOFF_O  2752512L
#define WTOT_   3014656L
__device__ __align__(256) __half g_Wf[WTOT_];

// ---------------------------------------------------------------------------
// Helpers
// ---------------------------------------------------------------------------
__device__ __forceinline__ uint32_t smem_u32(const void* p) {
    uint32_t a;
    asm("{ .reg .u64 t; cvta.to.shared.u64 t, %1; cvt.u32.u64 %0, t; }" : "=r"(a) : "l"(p));
    return a;
}
__device__ __forceinline__ void ldsm4(uint32_t* r, uint32_t addr) {
    asm volatile("ldmatrix.sync.aligned.m8n8.x4.shared.b16 {%0,%1,%2,%3}, [%4];"
        : "=r"(r[0]), "=r"(r[1]), "=r"(r[2]), "=r"(r[3]) : "r"(addr));
}
__device__ __forceinline__ void mma16816(float* d, const uint32_t* a, uint32_t b0, uint32_t b1) {
    asm volatile("mma.sync.aligned.m16n8k16.row.col.f32.f16.f16.f32 "
        "{%0,%1,%2,%3}, {%4,%5,%6,%7}, {%8,%9}, {%0,%1,%2,%3};"
        : "+f"(d[0]), "+f"(d[1]), "+f"(d[2]), "+f"(d[3])
        : "r"(a[0]), "r"(a[1]), "r"(a[2]), "r"(a[3]), "r"(b0), "r"(b1));
}
__device__ __forceinline__ void cpa16(uint32_t s, const void* g) {
    asm volatile("cp.async.ca.shared.global [%0], [%1], 16;" :: "r"(s), "l"(g));
}
#define CPA_COMMIT() asm volatile("cp.async.commit_group;" ::: "memory")
#define CPA_WAIT0()  asm volatile("cp.async.wait_group 0;" ::: "memory")

__device__ __forceinline__ uint32_t pkh(__half a, __half b) {
    unsigned short ra = *reinterpret_cast<unsigned short*>(&a);
    unsigned short rb = *reinterpret_cast<unsigned short*>(&b);
    return (uint32_t)ra | ((uint32_t)rb << 16);
}
__device__ __forceinline__ float gelu_f(float x) {
    return 0.5f * x * (1.0f + erff(x * 0.7071067811865476f));
}

// ---------------------------------------------------------------------------
// Conversion kernels
// ---------------------------------------------------------------------------
__global__ __launch_bounds__(256) void cvt_kernel(const float* __restrict__ x,
    __half* __restrict__ f, long n4)
{
    long i = (long)blockIdx.x * 256 + threadIdx.x;
    if (i >= n4) return;
    float4 v = reinterpret_cast<const float4*>(x)[i];
    reinterpret_cast<uint2*>(f)[i] = make_uint2(
        pkh(__float2half_rn(v.x), __float2half_rn(v.y)),
        pkh(__float2half_rn(v.z), __float2half_rn(v.w)));
}

// image_features [B, DIMG, SQ] -> A[m=b*SQ+q][k] fp16
__global__ __launch_bounds__(256) void if_cvt_kernel(const float* __restrict__ IF,
    __half* __restrict__ f) {
    __shared__ float sm[32][50];
    const int k0 = blockIdx.x * 32;
    const int b  = blockIdx.y;
    const float* base = IF + (long)b * DIMG_ * SQ_;
    for (int i = threadIdx.x; i < 32 * SQ_; i += 256) {
        int ky = i / SQ_, q = i - ky * SQ_;
        sm[ky][q] = base[(long)(k0 + ky) * SQ_ + q];
    }
    __syncthreads();
    for (int i = threadIdx.x; i < SQ_ * 32; i += 256) {
        int q = i >> 5, ky = i & 31;
        f[((long)(b * SQ_ + q)) * DIMG_ + k0 + ky] = __float2half_rn(sm[ky][q]);
    }
}

// W [K, 512] -> Wt[n][k] fp16
__global__ __launch_bounds__(256) void wt_cvt_kernel(const float* __restrict__ W,
    __half* __restrict__ tf, int K) {
    __shared__ float sm[32][33];
    const int k0 = blockIdx.x * 32;
    const int n0 = blockIdx.y * 32;
    for (int i = threadIdx.x; i < 1024; i += 256) {
        int r = i >> 5, c = i & 31;
        sm[r][c] = W[(long)(k0 + r) * D_ + n0 + c];
    }
    __syncthreads();
    for (int i = threadIdx.x; i < 1024; i += 256) {
        int r = i >> 5, c = i & 31;
        tf[(long)(n0 + r) * K + k0 + c] = __float2half_rn(sm[c][r]);
    }
}

// ---------------------------------------------------------------------------
// fp16 tensor-core GEMM: C = A(fp16) @ W(fp16) + bias (+Res), fp32 accum.
// CTA 128x128, K-chunk 64, 8 warps (warp tile 64x32), cp.async double buffer.
// Smem rows 144B (128B data + 16 pad) -> conflict-free ldmatrix.
// EPI: 0 = fp32 C. 1 = fp32 C AND gelu->fp16 into Of.
// ---------------------------------------------------------------------------
#define ROWB_   144
#define TILEB_  (128*ROWB_)     // 18432
#define OFF_B   TILEB_
#define STAGE_  (2*TILEB_)      // 36864
#define SMEM_G  (2*STAGE_)      // 73728

__device__ __forceinline__ void stage_cp(uint32_t sb,
    const __half* __restrict__ Af, const __half* __restrict__ Bf,
    int m0, int n0, int K, int kt, int tid)
{
    #pragma unroll
    for (int i = 0; i < 4; i++) {
        const int idx = tid + (i << 8);      // 0..1023
        const int row = idx >> 3, seg = idx & 7;
        const long ga = (long)(m0 + row) * K + kt + (seg << 3);
        const long gb = (long)(n0 + row) * K + kt + (seg << 3);
        const uint32_t so = row * ROWB_ + (seg << 4);
        cpa16(sb + so,         Af + ga);
        cpa16(sb + OFF_B + so, Bf + gb);
    }
}

__device__ __forceinline__ void compute_chunk(uint32_t sb, int wid, int lane, float acc[4][4][4])
{
    const int wm = (wid & 1) << 6;
    const int wn = (wid >> 1) << 5;
    #pragma unroll
    for (int ks = 0; ks < 4; ks++) {
        uint32_t bf[2][4];
        #pragma unroll
        for (int p = 0; p < 2; p++) {
            const int row = wn + (p << 4) + (lane & 7) + (((lane >> 4) & 1) << 3);
            const int cb  = (lane >> 3) & 1;
            ldsm4(bf[p], sb + OFF_B + row * ROWB_ + (ks << 5) + (cb << 4));
        }
        #pragma unroll
        for (int mt = 0; mt < 4; mt++) {
            const int row = wm + (mt << 4) + (lane & 15);
            const int cb  = lane >> 4;
            uint32_t af[4];
            ldsm4(af, sb + row * ROWB_ + (ks << 5) + (cb << 4));
            #pragma unroll
            for (int nt2 = 0; nt2 < 4; nt2++) {
                mma16816(acc[mt][nt2], af,
                         bf[nt2 >> 1][(nt2 & 1) << 1],
                         bf[nt2 >> 1][((nt2 & 1) << 1) + 1]);
            }
        }
    }
}

template<int EPI, bool RES>
__global__ __launch_bounds__(256, 2) void mma_gemm_kernel(
    const __half* __restrict__ Af, const __half* __restrict__ Bf,
    const float* __restrict__ bias, const float* __restrict__ Res,
    float* __restrict__ C, __half* __restrict__ Of, int K)
{
    extern __shared__ __align__(16) char smem[];
    const uint32_t sbase = smem_u32(smem);
    const int tid  = threadIdx.x;
    const int wid  = tid >> 5;
    const int lane = tid & 31;
    const int m0 = blockIdx.y * 128;
    const int n0 = blockIdx.x * 128;

    float acc[4][4][4];
    #pragma unroll
    for (int i = 0; i < 4; i++)
        #pragma unroll
        for (int j = 0; j < 4; j++)
            #pragma unroll
            for (int k = 0; k < 4; k++) acc[i][j][k] = 0.f;

    const int nt = K >> 6;

    stage_cp(sbase, Af, Bf, m0, n0, K, 0, tid);
    CPA_COMMIT();

    for (int t = 0; t < nt; t++) {
        const int cur = t & 1;
        CPA_WAIT0();
        __syncthreads();
        if (t + 1 < nt) {
            stage_cp(sbase + (cur ^ 1) * STAGE_, Af, Bf, m0, n0, K, (t + 1) << 6, tid);
            CPA_COMMIT();
        }
        compute_chunk(sbase + cur * STAGE_, wid, lane, acc);
        __syncthreads();
    }

    // Epilogue
    const int wm = (wid & 1) << 6;
    const int wn = (wid >> 1) << 5;
    #pragma unroll
    for (int mt = 0; mt < 4; mt++) {
        const int r0 = m0 + wm + (mt << 4) + (lane >> 2);
        #pragma unroll
        for (int nt2 = 0; nt2 < 4; nt2++) {
            const int cc = n0 + wn + (nt2 << 3) + ((lane & 3) << 1);
            const float2 bv = *reinterpret_cast<const float2*>(bias + cc);
            float2 o0, o1;
            o0.x = acc[mt][nt2][0] + bv.x; o0.y = acc[mt][nt2][1] + bv.y;
            o1.x = acc[mt][nt2][2] + bv.x; o1.y = acc[mt][nt2][3] + bv.y;
            if (RES) {
                const float2 r0v = *reinterpret_cast<const float2*>(Res + (long)r0 * D_ + cc);
                const float2 r1v = *reinterpret_cast<const float2*>(Res + (long)(r0 + 8) * D_ + cc);
                o0.x += r0v.x; o0.y += r0v.y; o1.x += r1v.x; o1.y += r1v.y;
            }
            *reinterpret_cast<float2*>(C + (long)r0 * D_ + cc)       = o0;
            *reinterpret_cast<float2*>(C + (long)(r0 + 8) * D_ + cc) = o1;
            if (EPI == 1) {
                *reinterpret_cast<uint32_t*>(Of + (long)r0 * D_ + cc) =
                    pkh(__float2half_rn(gelu_f(o0.x)), __float2half_rn(gelu_f(o0.y)));
                *reinterpret_cast<uint32_t*>(Of + (long)(r0 + 8) * D_ + cc) =
                    pkh(__float2half_rn(gelu_f(o1.x)), __float2half_rn(gelu_f(o1.y)));
            }
        }
    }
}

// ---------------------------------------------------------------------------
// LayerNorm in-place + fused fp16 convert
// ---------------------------------------------------------------------------
__global__ __launch_bounds__(128) void ln_cvt_kernel(
    float* __restrict__ X, const float* __restrict__ g, const float* __restrict__ be,
    __half* __restrict__ Of)
{
    const long row = blockIdx.x;
    float* xr = X + row * D_;
    const int t = threadIdx.x;
    float4 v = *reinterpret_cast<const float4*>(xr + t * 4);
    float s  = v.x + v.y + v.z + v.w;
    float sq = v.x*v.x + v.y*v.y + v.z*v.z + v.w*v.w;
    #pragma unroll
    for (int o = 16; o; o >>= 1) {
        s  += __shfl_xor_sync(0xffffffffu, s,  o);
        sq += __shfl_xor_sync(0xffffffffu, sq, o);
    }
    __shared__ float sh[8];
    if ((t & 31) == 0) { sh[t >> 5] = s; sh[4 + (t >> 5)] = sq; }
    __syncthreads();
    const float ts = sh[0] + sh[1] + sh[2] + sh[3];
    const float tq = sh[4] + sh[5] + sh[6] + sh[7];
    const float mu  = ts * (1.f / 512.f);
    const float var = tq * (1.f / 512.f) - mu * mu;
    const float inv = rsqrtf(var + 1e-5f);
    float4 gv = *reinterpret_cast<const float4*>(g  + t * 4);
    float4 bv = *reinterpret_cast<const float4*>(be + t * 4);
    v.x = gv.x * (v.x - mu) * inv + bv.x;
    v.y = gv.y * (v.y - mu) * inv + bv.y;
    v.z = gv.z * (v.z - mu) * inv + bv.z;
    v.w = gv.w * (v.w - mu) * inv + bv.w;
    *reinterpret_cast<float4*>(xr + t * 4) = v;
    reinterpret_cast<uint2*>(Of + row * D_)[t] = make_uint2(
        pkh(__float2half_rn(v.x), __float2half_rn(v.y)),
        pkh(__float2half_rn(v.z), __float2half_rn(v.w)));
}

// ---------------------------------------------------------------------------
// Attention per (b,h); writes probs + fp16 output
// ---------------------------------------------------------------------------
__global__ __launch_bounds__(256) void attn_kernel(
    const float* __restrict__ q, const float* __restrict__ k,
    const float* __restrict__ v, float* __restrict__ a,
    __half* __restrict__ of)
{
    const int bh = blockIdx.x;
    const int b  = bh >> 2;
    const int h  = bh & 3;
    __shared__ float kv[SK_ * DH_];
    __shared__ float s[SQ_ * SK_];
    const int tid = threadIdx.x;

    const float* kb = k + (long)b * SK_ * D_ + h * DH_;
    for (int i = tid; i < SK_ * DH_; i += 256) {
        int r = i >> 7, d = i & 127;
        kv[i] = kb[(long)r * D_ + d];
    }
    __syncthreads();

    const float* qb = q + (long)b * SQ_ * D_ + h * DH_;
    for (int i = tid; i < SQ_ * SK_; i += 256) {
        int qi = i / SK_, ki = i - qi * SK_;
        const float* qr = qb + (long)qi * D_;
        const float* kr = kv + ki * DH_;
        float accv = 0.f;
        #pragma unroll 8
        for (int d = 0; d < DH_; d++) accv += qr[d] * kr[d];
        s[i] = accv * 0.08838834764831845f;
    }
    __syncthreads();

    const float* vb = v + (long)b * SK_ * D_ + h * DH_;
    for (int i = tid; i < SK_ * DH_; i += 256) {
        int r = i >> 7, d = i & 127;
        kv[i] = vb[(long)r * D_ + d];
    }
    const int w = tid >> 5, lane = tid & 31;
    for (int row = w; row < SQ_; row += 8) {
        float mx = -1e30f;
        for (int c = lane; c < SK_; c += 32) mx = fmaxf(mx, s[row * SK_ + c]);
        #pragma unroll
        for (int off = 16; off; off >>= 1) mx = fmaxf(mx, __shfl_xor_sync(0xffffffffu, mx, off));
        float sum = 0.f;
        for (int c = lane; c < SK_; c += 32) {
            float e = __expf(s[row * SK_ + c] - mx);
            s[row * SK_ + c] = e;
            sum += e;
        }
        #pragma unroll
        for (int off = 16; off; off >>= 1) sum += __shfl_xor_sync(0xffffffffu, sum, off);
        const float inv = 1.f / sum;
        float* arow = a + ((long)(b * H_ + h) * SQ_ + row) * SK_;
        for (int c = lane; c < SK_; c += 32) {
            float p = s[row * SK_ + c] * inv;
            s[row * SK_ + c] = p;
            arow[c] = p;
        }
    }
    __syncthreads();

    for (int i = tid; i < SQ_ * DH_; i += 256) {
        int qi = i >> 7, d = i & 127;
        const float* sr = s + qi * SK_;
        float accv = 0.f;
        #pragma unroll
        for (int kk = 0; kk < SK_; kk++) accv += sr[kk] * kv[kk * DH_ + d];
        of[((long)b * SQ_ + qi) * D_ + h * DH_ + d] = __float2half_rn(accv);
    }
}

__global__ void meanh_kernel(const float* __restrict__ a, float* __restrict__ out)
{
    const int idx = blockIdx.x * 256 + threadIdx.x;
    if (idx >= B_ * SQ_ * SK_) return;
    const int b = idx / (SQ_ * SK_);
    const int r = idx - b * (SQ_ * SK_);
    float sum = 0.f;
    #pragma unroll
    for (int h = 0; h < H_; h++)
        sum += a[((long)(b * H_ + h)) * (SQ_ * SK_) + r];
    out[idx] = sum * 0.25f;
}

__global__ __launch_bounds__(256) void norm_kernel(
    const float* __restrict__ ao, const float* __restrict__ pt,
    float* __restrict__ n1, float* __restrict__ n2)
{
    const int b = blockIdx.x;
    const int t = threadIdx.x;
    float v1[2], v2[2];
    float sq1 = 0.f, sq2 = 0.f;
    #pragma unroll
    for (int j = 0; j < 2; j++) {
        const int d = t + j * 256;
        const float* base = ao + (long)b * SQ_ * D_ + d;
        float sum = 0.f;
        #pragma unroll
        for (int qq = 0; qq < SQ_; qq++) sum += base[(long)qq * D_];
        sum *= (1.f / 49.f);
        v1[j] = sum; sq1 += sum * sum;
        const float c = pt[(long)b * SK_ * D_ + d];
        v2[j] = c; sq2 += c * c;
    }
    #pragma unroll
    for (int o = 16; o; o >>= 1) {
        sq1 += __shfl_xor_sync(0xffffffffu, sq1, o);
        sq2 += __shfl_xor_sync(0xffffffffu, sq2, o);
    }
    __shared__ float s1[8], s2[8];
    if ((t & 31) == 0) { s1[t >> 5] = sq1; s2[t >> 5] = sq2; }
    __syncthreads();
    float t1 = 0.f, t2 = 0.f;
    #pragma unroll
    for (int i = 0; i < 8; i++) { t1 += s1[i]; t2 += s2[i]; }
    const float i1 = rsqrtf(t1), i2 = rsqrtf(t2);
    #pragma unroll
    for (int j = 0; j < 2; j++) {
        const int d = t + j * 256;
        n1[(long)b * D_ + d] = v1[j] * i1;
        n2[(long)b * D_ + d] = v2[j] * i2;
    }
}

__global__ __launch_bounds__(256) void score_kernel(
    const float* __restrict__ n1, const float* __restrict__ n2, float* __restrict__ out)
{
    __shared__ float As[16][17];
    __shared__ float Bs[16][17];
    const int tx = threadIdx.x & 15;
    const int ty = threadIdx.x >> 4;
    const int i0 = blockIdx.y * 16;
    const int j0 = blockIdx.x * 16;
    float acc = 0.f;
    for (int k0 = 0; k0 < D_; k0 += 16) {
        As[ty][tx] = n1[(long)(i0 + ty) * D_ + k0 + tx];
        Bs[ty][tx] = n2[(long)(j0 + ty) * D_ + k0 + tx];
        __syncthreads();
        #pragma unroll
        for (int e = 0; e < 16; e++) acc += As[ty][e] * Bs[tx][e];
        __syncthreads();
    }
    out[(long)(i0 + ty) * B_ + j0 + tx] = acc;
}

// ---------------------------------------------------------------------------
extern "C" void kernel_launch(void* const* d_in, const int* in_sizes, int n_in,
                              void* d_out, int out_size)
{
    (void)in_sizes; (void)n_in; (void)out_size;
    const float* IF  = (const float*)d_in[0];
    const float* TXT = (const float*)d_in[1];
    const float* Wi1 = (const float*)d_in[2];
    const float* bi1 = (const float*)d_in[3];
    const float* Wi2 = (const float*)d_in[4];
    const float* bi2 = (const float*)d_in[5];
    const float* gi  = (const float*)d_in[6];
    const float* bei = (const float*)d_in[7];
    const float* Wt1 = (const float*)d_in[8];
    const float* bt1 = (const float*)d_in[9];
    const float* Wt2 = (const float*)d_in[10];
    const float* bt2 = (const float*)d_in[11];
    const float* gt  = (const float*)d_in[12];
    const float* bet = (const float*)d_in[13];
    const float* Wq  = (const float*)d_in[14];
    const float* bq  = (const float*)d_in[15];
    const float* Wk  = (const float*)d_in[16];
    const float* bk  = (const float*)d_in[17];
    const float* Wv  = (const float*)d_in[18];
    const float* bv  = (const float*)d_in[19];
    const float* Wo  = (const float*)d_in[20];
    const float* bo  = (const float*)d_in[21];

    float* out       = (float*)d_out;
    float* score     = out;
    float* attn_out  = score + (long)B_ * B_;
    float* attn_w    = attn_out + (long)MI_ * D_;
    float* pi        = attn_w + (long)B_ * SQ_ * SK_;
    float* pt        = pi + (long)MI_ * D_;

    float *Pimg, *Ptxt, *qb_, *kb_, *vb_, *ab_, *n1_, *n2_;
    __half *Af, *pif, *ptf, *Wf;
    cudaGetSymbolAddress((void**)&Pimg, g_Pimg);
    cudaGetSymbolAddress((void**)&Ptxt, g_Ptxt);
    cudaGetSymbolAddress((void**)&qb_,  g_q);
    cudaGetSymbolAddress((void**)&kb_,  g_k);
    cudaGetSymbolAddress((void**)&vb_,  g_v);
    cudaGetSymbolAddress((void**)&ab_,  g_a);
    cudaGetSymbolAddress((void**)&n1_,  g_n1);
    cudaGetSymbolAddress((void**)&n2_,  g_n2);
    cudaGetSymbolAddress((void**)&Af,   g_Af);
    cudaGetSymbolAddress((void**)&pif,  g_pif);
    cudaGetSymbolAddress((void**)&ptf,  g_ptf);
    cudaGetSymbolAddress((void**)&Wf,   g_Wf);

    cudaFuncSetAttribute(mma_gemm_kernel<0,false>, cudaFuncAttributeMaxDynamicSharedMemorySize, SMEM_G);
    cudaFuncSetAttribute(mma_gemm_kernel<0,true>,  cudaFuncAttributeMaxDynamicSharedMemorySize, SMEM_G);
    cudaFuncSetAttribute(mma_gemm_kernel<1,false>, cudaFuncAttributeMaxDynamicSharedMemorySize, SMEM_G);

    const dim3 gI(4, MI_ / 128);   // (4, 196)
    const dim3 gT(4, MT_ / 128);   // (4, 200)

    // Launches 0-4 (ncu -s 5 skips these); launch 5 = big image GEMM.
    wt_cvt_kernel<<<dim3(DIMG_/32, 16), 256>>>(Wi1, Wf + WOFF_I1, DIMG_);  // 0
    if_cvt_kernel<<<dim3(DIMG_/32, B_), 256>>>(IF, Af);                    // 1
    wt_cvt_kernel<<<dim3(DTXT_/32, 16), 256>>>(Wt1, Wf + WOFF_T1, DTXT_);  // 2
    wt_cvt_kernel<<<dim3(D_/32, 16), 256>>>(Wi2, Wf + WOFF_I2, D_);        // 3
    wt_cvt_kernel<<<dim3(D_/32, 16), 256>>>(Wt2, Wf + WOFF_T2, D_);        // 4

    // 5: image GEMM1 (K=2048) — ncu capture target
    mma_gemm_kernel<1,false><<<gI, 256, SMEM_G>>>(Af, Wf+WOFF_I1, bi1, nullptr, Pimg, pif, DIMG_);
    mma_gemm_kernel<0,true ><<<gI, 256, SMEM_G>>>(pif, Wf+WOFF_I2, bi2, Pimg, pi, nullptr, D_);
    ln_cvt_kernel<<<MI_, 128>>>(pi, gi, bei, pif);

    // Text head
    cvt_kernel<<<((long)MT_*DTXT_/4 + 255)/256, 256>>>(TXT, Af, (long)MT_*DTXT_/4);
    mma_gemm_kernel<1,false><<<gT, 256, SMEM_G>>>(Af, Wf+WOFF_T1, bt1, nullptr, Ptxt, ptf, DTXT_);
    mma_gemm_kernel<0,true ><<<gT, 256, SMEM_G>>>(ptf, Wf+WOFF_T2, bt2, Ptxt, pt, nullptr, D_);
    ln_cvt_kernel<<<MT_, 128>>>(pt, gt, bet, ptf);

    // Remaining weight converts
    wt_cvt_kernel<<<dim3(D_/32, 16), 256>>>(Wq, Wf + WOFF_Q, D_);
    wt_cvt_kernel<<<dim3(D_/32, 16), 256>>>(Wk, Wf + WOFF_K, D_);
    wt_cvt_kernel<<<dim3(D_/32, 16), 256>>>(Wv, Wf + WOFF_V, D_);
    wt_cvt_kernel<<<dim3(D_/32, 16), 256>>>(Wo, Wf + WOFF_O, D_);

    // QKV
    mma_gemm_kernel<0,false><<<gI, 256, SMEM_G>>>(pif, Wf+WOFF_Q, bq, nullptr, qb_, nullptr, D_);
    mma_gemm_kernel<0,false><<<gT, 256, SMEM_G>>>(ptf, Wf+WOFF_K, bk, nullptr, kb_, nullptr, D_);
    mma_gemm_kernel<0,false><<<gT, 256, SMEM_G>>>(ptf, Wf+WOFF_V, bv, nullptr, vb_, nullptr, D_);

    // Attention (writes probs + fp16 o into Af)
    attn_kernel<<<B_ * H_, 256>>>(qb_, kb_, vb_, ab_, Af);
    meanh_kernel<<<(B_ * SQ_ * SK_ + 255) / 256, 256>>>(ab_, attn_w);

    // Output projection
    mma_gemm_kernel<0,false><<<gI, 256, SMEM_G>>>(Af, Wf+WOFF_O, bo, nullptr, attn_out, nullptr, D_);

    // Normalized similarity
    norm_kernel<<<B_, 256>>>(attn_out, pt, n1_, n2_);
    score_kernel<<<dim3(B_ / 16, B_ / 16), 256>>>(n1_, n2_, score);
}